// round 2
// baseline (speedup 1.0000x reference)
#include <cuda_runtime.h>
#include <cuda_bf16.h>
#include <math.h>

// Problem dims
#define BB   64
#define TT   2048
#define ENC  512
#define DEC  512
#define UU   128
#define BT   (BB*TT)          // 131072 rows
#define NSPLIT 8              // context T-splits

// Scratch (allocation-free rule: __device__ globals)
__device__ float g_q[BB * UU];                 // q + ba + bb, [B][U]
__device__ float g_scores[BT];                 // pre-softmax scores [B][T]
__device__ float g_pctx[BB * NSPLIT * ENC];    // partial contexts

// ---------------------------------------------------------------------------
// K0: q[b][u] = dh[b] @ Wa[:,u] + ba[u] + bb[u]
// ---------------------------------------------------------------------------
__global__ void q_kernel(const float* __restrict__ dh,
                         const float* __restrict__ Wa,
                         const float* __restrict__ ba,
                         const float* __restrict__ bb) {
    int b = blockIdx.x;
    int u = threadIdx.x;          // 128 threads
    float acc = ba[u] + bb[u];
    const float* dhb = dh + b * DEC;
    #pragma unroll 8
    for (int e = 0; e < DEC; e++) {
        acc = fmaf(dhb[e], Wa[e * UU + u], acc);
    }
    g_q[b * UU + u] = acc;
}

// ---------------------------------------------------------------------------
// K1: scores. GEMM k = E @ Wb tiled BM=128, BN=128, BK=32, fused epilogue
//     s[row] = sum_u Wv[u] * tanh(q[b][u] + k[row][u]) + bv
// grid = BT/128 = 1024 blocks, 256 threads, 8x8 microtile
// ---------------------------------------------------------------------------
#define BM 128
#define BN 128
#define BK 32
#define APAD 4   // As row stride = BM+APAD = 132 floats (multiple of 4 -> float4 ok)

__global__ void __launch_bounds__(256, 2)
scores_kernel(const float* __restrict__ E,
              const float* __restrict__ Wb,
              const float* __restrict__ Wv,
              const float* __restrict__ bv) {
    __shared__ float As[BK][BM + APAD];   // transposed A tile: As[k][row]
    __shared__ float Bs[BK][BN];          // Bs[k][u]
    __shared__ float red[BM][17];         // row-reduction scratch (pad 17)

    const int tid = threadIdx.x;
    const int tx  = tid & 15;            // u-col group (0..15) -> cols tx*8..+7
    const int ty  = tid >> 4;            // row group   (0..15) -> rows ty*8..+7
    const int row0 = blockIdx.x * BM;    // global row base (tile never crosses b)
    const float* Eb = E + (size_t)row0 * ENC;

    float acc[8][8];
    #pragma unroll
    for (int i = 0; i < 8; i++)
        #pragma unroll
        for (int j = 0; j < 8; j++) acc[i][j] = 0.f;

    for (int k0 = 0; k0 < ENC; k0 += BK) {
        // ---- load A tile (128 rows x 32 k), transposed into As[k][row]
        #pragma unroll
        for (int it = 0; it < 4; it++) {
            int i  = tid + it * 256;      // 0..1023 float4 items
            int r  = i >> 3;              // row 0..127
            int kq = i & 7;               // float4 index along k
            float4 v = *(const float4*)(Eb + (size_t)r * ENC + k0 + kq * 4);
            As[kq * 4 + 0][r] = v.x;
            As[kq * 4 + 1][r] = v.y;
            As[kq * 4 + 2][r] = v.z;
            As[kq * 4 + 3][r] = v.w;
        }
        // ---- load B tile (32 k x 128 u)
        #pragma unroll
        for (int it = 0; it < 4; it++) {
            int i  = tid + it * 256;
            int kk = i >> 5;              // 0..31
            int uq = i & 31;              // float4 index along u
            float4 v = *(const float4*)(Wb + (size_t)(k0 + kk) * UU + uq * 4);
            *(float4*)&Bs[kk][uq * 4] = v;
        }
        __syncthreads();

        // ---- FMA
        #pragma unroll
        for (int k = 0; k < BK; k++) {
            float a[8], bvec[8];
            *(float4*)(a)     = *(const float4*)&As[k][ty * 8];
            *(float4*)(a + 4) = *(const float4*)&As[k][ty * 8 + 4];
            *(float4*)(bvec)     = *(const float4*)&Bs[k][tx * 8];
            *(float4*)(bvec + 4) = *(const float4*)&Bs[k][tx * 8 + 4];
            #pragma unroll
            for (int i = 0; i < 8; i++)
                #pragma unroll
                for (int j = 0; j < 8; j++)
                    acc[i][j] = fmaf(a[i], bvec[j], acc[i][j]);
        }
        __syncthreads();
    }

    // ---- epilogue: per-row  sum_u Wv[u]*tanh(q+k)
    const int b = row0 >> 11;            // row0 / 2048
    float qv[8], wv[8];
    #pragma unroll
    for (int j = 0; j < 8; j++) {
        int u = tx * 8 + j;
        qv[j] = g_q[b * UU + u];
        wv[j] = Wv[u];
    }
    #pragma unroll
    for (int i = 0; i < 8; i++) {
        float p = 0.f;
        #pragma unroll
        for (int j = 0; j < 8; j++)
            p = fmaf(wv[j], tanhf(qv[j] + acc[i][j]), p);
        red[ty * 8 + i][tx] = p;
    }
    __syncthreads();
    if (tid < BM) {
        float s = 0.f;
        #pragma unroll
        for (int x = 0; x < 16; x++) s += red[tid][x];
        g_scores[row0 + tid] = s + bv[0];
    }
}

// ---------------------------------------------------------------------------
// K2: softmax over T per batch row. grid=64, block=256. attn -> out
// ---------------------------------------------------------------------------
__global__ void softmax_kernel(float* __restrict__ attn_out) {
    __shared__ float sred[256];
    const int b   = blockIdx.x;
    const int tid = threadIdx.x;
    const float* sc = g_scores + b * TT;

    float ls[8];
    float m = -1e30f;
    #pragma unroll
    for (int i = 0; i < 8; i++) {
        ls[i] = sc[tid + i * 256];
        m = fmaxf(m, ls[i]);
    }
    sred[tid] = m;
    __syncthreads();
    for (int off = 128; off > 0; off >>= 1) {
        if (tid < off) sred[tid] = fmaxf(sred[tid], sred[tid + off]);
        __syncthreads();
    }
    m = sred[0];
    __syncthreads();

    float sum = 0.f;
    #pragma unroll
    for (int i = 0; i < 8; i++) {
        ls[i] = __expf(ls[i] - m);
        sum += ls[i];
    }
    sred[tid] = sum;
    __syncthreads();
    for (int off = 128; off > 0; off >>= 1) {
        if (tid < off) sred[tid] += sred[tid + off];
        __syncthreads();
    }
    const float inv = 1.f / sred[0];

    float* ao = attn_out + b * TT;
    #pragma unroll
    for (int i = 0; i < 8; i++)
        ao[tid + i * 256] = ls[i] * inv;
}

// ---------------------------------------------------------------------------
// K3: partial context. grid=(NSPLIT, B), block=512 (one thread per enc dim).
// ---------------------------------------------------------------------------
__global__ void pctx_kernel(const float* __restrict__ E,
                            const float* __restrict__ attn) {
    __shared__ float sp[TT / NSPLIT];    // 256 probs
    const int split = blockIdx.x;
    const int b     = blockIdx.y;
    const int e     = threadIdx.x;       // 0..511
    const int t0    = split * (TT / NSPLIT);

    if (threadIdx.x < TT / NSPLIT)
        sp[threadIdx.x] = attn[b * TT + t0 + threadIdx.x];
    __syncthreads();

    const float* Ebt = E + ((size_t)b * TT + t0) * ENC + e;
    float acc = 0.f;
    #pragma unroll 4
    for (int t = 0; t < TT / NSPLIT; t++)
        acc = fmaf(sp[t], Ebt[(size_t)t * ENC], acc);

    g_pctx[(b * NSPLIT + split) * ENC + e] = acc;
}

// ---------------------------------------------------------------------------
// K4: reduce partial contexts. grid=64, block=512.
// ---------------------------------------------------------------------------
__global__ void ctx_reduce_kernel(float* __restrict__ ctx_out) {
    const int b = blockIdx.x;
    const int e = threadIdx.x;
    float s = 0.f;
    #pragma unroll
    for (int sp = 0; sp < NSPLIT; sp++)
        s += g_pctx[(b * NSPLIT + sp) * ENC + e];
    ctx_out[b * ENC + e] = s;
}

// ---------------------------------------------------------------------------
extern "C" void kernel_launch(void* const* d_in, const int* in_sizes, int n_in,
                              void* d_out, int out_size) {
    const float* dh = (const float*)d_in[0];   // [64,512]
    const float* E  = (const float*)d_in[1];   // [64,2048,512]
    const float* Wa = (const float*)d_in[2];   // [512,128]
    const float* ba = (const float*)d_in[3];   // [128]
    const float* Wb = (const float*)d_in[4];   // [512,128]
    const float* bb = (const float*)d_in[5];   // [128]
    const float* Wv = (const float*)d_in[6];   // [128,1]
    const float* bv = (const float*)d_in[7];   // [1]

    float* out      = (float*)d_out;
    float* ctx_out  = out;                     // [64,512]
    float* attn_out = out + BB * ENC;          // [64,2048]

    q_kernel<<<BB, UU>>>(dh, Wa, ba, bb);
    scores_kernel<<<BT / BM, 256>>>(E, Wb, Wv, bv);
    softmax_kernel<<<BB, 256>>>(attn_out);
    pctx_kernel<<<dim3(NSPLIT, BB), ENC>>>(E, attn_out);
    ctx_reduce_kernel<<<BB, ENC>>>(ctx_out);
}

// round 4
// speedup vs baseline: 1.8429x; 1.8429x over previous
#include <cuda_runtime.h>
#include <cuda_bf16.h>
#include <math.h>

// Problem dims
#define BB   64
#define TT   2048
#define ENC  512
#define DEC  512
#define UU   128
#define BT   (BB*TT)

// scratch (__device__ globals per allocation-free rule)
__device__ float g_q[BB * UU];            // q + ba + bb
__device__ float g_ctx_part[128 * ENC];   // per-(b,half) unnormalized context
__device__ float g_l_part[128];           // per-(b,half) sum of exp(s)
__device__ float g_linv[BB];              // 1/l per batch

// ---------------------------------------------------------------------------
// K0: q[b][u] = dh[b] @ Wa[:,u] + ba[u] + bb[u]
// ---------------------------------------------------------------------------
__global__ void q_kernel(const float* __restrict__ dh,
                         const float* __restrict__ Wa,
                         const float* __restrict__ ba,
                         const float* __restrict__ bb) {
    int b = blockIdx.x;
    int u = threadIdx.x;          // 128 threads
    float acc = ba[u] + bb[u];
    const float* dhb = dh + b * DEC;
    #pragma unroll 8
    for (int e = 0; e < DEC; e++)
        acc = fmaf(dhb[e], Wa[e * UU + u], acc);
    g_q[b * UU + u] = acc;
}

// ---------------------------------------------------------------------------
// tf32 helpers
// ---------------------------------------------------------------------------
__device__ __forceinline__ float to_tf32(float f) {
    unsigned u;
    asm("cvt.rna.tf32.f32 %0, %1;" : "=r"(u) : "f"(f));
    return __uint_as_float(u);
}

__device__ __forceinline__ void mma_tf32(float& c0, float& c1, float& c2, float& c3,
                                         float a0, float a1, float a2, float a3,
                                         float b0, float b1) {
    asm volatile(
        "mma.sync.aligned.m16n8k8.row.col.f32.tf32.tf32.f32 "
        "{%0,%1,%2,%3}, {%4,%5,%6,%7}, {%8,%9}, {%0,%1,%2,%3};\n"
        : "+f"(c0), "+f"(c1), "+f"(c2), "+f"(c3)
        : "r"(__float_as_uint(a0)), "r"(__float_as_uint(a1)),
          "r"(__float_as_uint(a2)), "r"(__float_as_uint(a3)),
          "r"(__float_as_uint(b0)), "r"(__float_as_uint(b1)));
}

// ---------------------------------------------------------------------------
// K1 (fused): per CTA = one (b, half) pair, T-chunk = 1024 rows.
//   For each 128-row tile:
//     1. k = E_tile @ Wb via tf32 mma (double-buffered smem)
//     2. s = Wv . tanh(q + k) + bv ; p = exp(s)  (no max needed: |s| <= ~9)
//     3. write p -> attn_out ; l += p ; ctx += p * E_tile (E re-read, L2-hot)
// ---------------------------------------------------------------------------
#define ASTRIDE 36      // 32 + 4 pad  (A frag LDS conflict-free)
#define BSTRIDE 136     // 128 + 8 pad (B frag LDS conflict-free)
#define A_TILE (128 * ASTRIDE)      // floats
#define B_TILE (32 * BSTRIDE)       // floats
#define DYN_FLOATS (2 * A_TILE + 2 * B_TILE)

extern __shared__ float dynsmem[];

__global__ void __launch_bounds__(256, 1)
fused_kernel(const float* __restrict__ E,
             const float* __restrict__ Wb,
             const float* __restrict__ Wv,
             const float* __restrict__ bv,
             float* __restrict__ attn_out) {
    __shared__ float p_tile[128];
    __shared__ float q_s[UU], wv_s[UU];
    __shared__ float red[256];

    const int tid  = threadIdx.x;
    const int lane = tid & 31;
    const int w    = tid >> 5;          // warp 0..7
    const int b    = blockIdx.x >> 1;
    const int half = blockIdx.x & 1;

    float* AsBuf = dynsmem;                    // [2][A_TILE]
    float* BsBuf = dynsmem + 2 * A_TILE;       // [2][B_TILE]

    if (tid < UU) { q_s[tid] = g_q[b * UU + tid]; wv_s[tid] = Wv[tid]; }
    const float bv0 = bv[0];

    float2 ctx = make_float2(0.f, 0.f);
    float  l_acc = 0.f;

    const size_t rowbase = (size_t)b * TT + (size_t)half * 1024;

    for (int tile = 0; tile < 8; tile++) {
        const float* Ebt = E + (rowbase + tile * 128) * ENC;

        float acc[16][4];
        #pragma unroll
        for (int j = 0; j < 16; j++)
            { acc[j][0]=0.f; acc[j][1]=0.f; acc[j][2]=0.f; acc[j][3]=0.f; }

        // ---- preload k0 = 0 into buffer 0
        {
            float* As = AsBuf;
            float* Bs = BsBuf;
            #pragma unroll
            for (int it = 0; it < 4; it++) {
                int i  = tid + it * 256;
                int r  = i >> 3, kq = i & 7;
                float4 v = *(const float4*)(Ebt + (size_t)r * ENC + kq * 4);
                float4 o = make_float4(to_tf32(v.x), to_tf32(v.y), to_tf32(v.z), to_tf32(v.w));
                *(float4*)&As[r * ASTRIDE + kq * 4] = o;
            }
            #pragma unroll
            for (int it = 0; it < 4; it++) {
                int i  = tid + it * 256;
                int kk = i >> 5, uq = i & 31;
                float4 v = *(const float4*)(Wb + (size_t)kk * UU + uq * 4);
                float4 o = make_float4(to_tf32(v.x), to_tf32(v.y), to_tf32(v.z), to_tf32(v.w));
                *(float4*)&Bs[kk * BSTRIDE + uq * 4] = o;
            }
        }
        __syncthreads();

        // ---- K loop: 16 chunks of BK=32, double buffered
        for (int kt = 0; kt < 16; kt++) {
            const int cur = kt & 1;
            const float* As = AsBuf + cur * A_TILE;
            const float* Bs = BsBuf + cur * B_TILE;

            // prefetch next chunk (LDG only; STS after compute)
            float4 pa[4], pb[4];
            if (kt < 15) {
                const int k0 = (kt + 1) * 32;
                #pragma unroll
                for (int it = 0; it < 4; it++) {
                    int i = tid + it * 256;
                    int r = i >> 3, kq = i & 7;
                    pa[it] = *(const float4*)(Ebt + (size_t)r * ENC + k0 + kq * 4);
                }
                #pragma unroll
                for (int it = 0; it < 4; it++) {
                    int i = tid + it * 256;
                    int kk = i >> 5, uq = i & 31;
                    pb[it] = *(const float4*)(Wb + (size_t)(k0 + kk) * UU + uq * 4);
                }
            }

            // compute: 4 k-steps of 8
            const int arow = w * 16 + (lane >> 2);
            #pragma unroll
            for (int ks = 0; ks < 4; ks++) {
                const int acol = ks * 8 + (lane & 3);
                float a0 = As[arow * ASTRIDE + acol];
                float a1 = As[(arow + 8) * ASTRIDE + acol];
                float a2 = As[arow * ASTRIDE + acol + 4];
                float a3 = As[(arow + 8) * ASTRIDE + acol + 4];
                const int brow = ks * 8 + (lane & 3);
                const int bcol = lane >> 2;
                #pragma unroll
                for (int j = 0; j < 16; j++) {
                    float b0 = Bs[brow * BSTRIDE + j * 8 + bcol];
                    float b1 = Bs[(brow + 4) * BSTRIDE + j * 8 + bcol];
                    mma_tf32(acc[j][0], acc[j][1], acc[j][2], acc[j][3],
                             a0, a1, a2, a3, b0, b1);
                }
            }

            // store prefetched chunk into other buffer
            if (kt < 15) {
                float* Asn = AsBuf + (cur ^ 1) * A_TILE;
                float* Bsn = BsBuf + (cur ^ 1) * B_TILE;
                #pragma unroll
                for (int it = 0; it < 4; it++) {
                    int i = tid + it * 256;
                    int r = i >> 3, kq = i & 7;
                    float4 o = make_float4(to_tf32(pa[it].x), to_tf32(pa[it].y),
                                           to_tf32(pa[it].z), to_tf32(pa[it].w));
                    *(float4*)&Asn[r * ASTRIDE + kq * 4] = o;
                }
                #pragma unroll
                for (int it = 0; it < 4; it++) {
                    int i = tid + it * 256;
                    int kk = i >> 5, uq = i & 31;
                    float4 o = make_float4(to_tf32(pb[it].x), to_tf32(pb[it].y),
                                           to_tf32(pb[it].z), to_tf32(pb[it].w));
                    *(float4*)&Bsn[kk * BSTRIDE + uq * 4] = o;
                }
            }
            __syncthreads();
        }

        // ---- epilogue: s = Wv . tanh(q + k) + bv ; p = exp(s)
        float plo = 0.f, phi = 0.f;
        #pragma unroll
        for (int j = 0; j < 16; j++) {
            const int u0 = j * 8 + 2 * (lane & 3);
            plo = fmaf(wv_s[u0],     tanhf(q_s[u0]     + acc[j][0]), plo);
            plo = fmaf(wv_s[u0 + 1], tanhf(q_s[u0 + 1] + acc[j][1]), plo);
            phi = fmaf(wv_s[u0],     tanhf(q_s[u0]     + acc[j][2]), phi);
            phi = fmaf(wv_s[u0 + 1], tanhf(q_s[u0 + 1] + acc[j][3]), phi);
        }
        plo += __shfl_xor_sync(0xffffffffu, plo, 1);
        plo += __shfl_xor_sync(0xffffffffu, plo, 2);
        phi += __shfl_xor_sync(0xffffffffu, phi, 1);
        phi += __shfl_xor_sync(0xffffffffu, phi, 2);
        if ((lane & 3) == 0) {
            const int rl = w * 16 + (lane >> 2);          // row in tile (0..7 per warp grp)
            const float pl = __expf(plo + bv0);
            const float ph = __expf(phi + bv0);
            p_tile[rl]     = pl;
            p_tile[rl + 8] = ph;
            const size_t gr = rowbase + tile * 128 + rl;
            attn_out[gr]     = pl;
            attn_out[gr + 8] = ph;
            l_acc += pl + ph;
        }
        __syncthreads();

        // ---- context accumulation: ctx[e] += p_t * E[t][e]   (E re-read, L2-hot)
        const float2* E2 = (const float2*)Ebt;    // row stride = 256 float2
        #pragma unroll 4
        for (int t = 0; t < 128; t++) {
            const float pt = p_tile[t];
            const float2 v = E2[(size_t)t * 256 + tid];
            ctx.x = fmaf(pt, v.x, ctx.x);
            ctx.y = fmaf(pt, v.y, ctx.y);
        }
        __syncthreads();
    }

    // ---- write partials
    red[tid] = l_acc;
    __syncthreads();
    for (int off = 128; off > 0; off >>= 1) {
        if (tid < off) red[tid] += red[tid + off];
        __syncthreads();
    }
    if (tid == 0) g_l_part[blockIdx.x] = red[0];

    ((float2*)(g_ctx_part + (size_t)blockIdx.x * ENC))[tid] = ctx;
}

// ---------------------------------------------------------------------------
// K2: combine halves -> normalized context + 1/l
// ---------------------------------------------------------------------------
__global__ void combine_kernel(float* __restrict__ ctx_out) {
    const int b = blockIdx.x;
    const int e = threadIdx.x;   // 512
    const float l = g_l_part[2 * b] + g_l_part[2 * b + 1];
    const float linv = 1.f / l;
    ctx_out[b * ENC + e] =
        (g_ctx_part[(2 * b) * ENC + e] + g_ctx_part[(2 * b + 1) * ENC + e]) * linv;
    if (e == 0) g_linv[b] = linv;
}

// ---------------------------------------------------------------------------
// K3: normalize attn in place
// ---------------------------------------------------------------------------
__global__ void norm_kernel(float* __restrict__ attn) {
    const int i = blockIdx.x * blockDim.x + threadIdx.x;
    attn[i] *= g_linv[i >> 11];   // i / 2048
}

// ---------------------------------------------------------------------------
extern "C" void kernel_launch(void* const* d_in, const int* in_sizes, int n_in,
                              void* d_out, int out_size) {
    const float* dh = (const float*)d_in[0];
    const float* E  = (const float*)d_in[1];
    const float* Wa = (const float*)d_in[2];
    const float* ba = (const float*)d_in[3];
    const float* Wb = (const float*)d_in[4];
    const float* bb = (const float*)d_in[5];
    const float* Wv = (const float*)d_in[6];
    const float* bv = (const float*)d_in[7];

    float* out      = (float*)d_out;
    float* ctx_out  = out;                 // [64,512]
    float* attn_out = out + BB * ENC;      // [64,2048]

    const int dyn_bytes = DYN_FLOATS * sizeof(float);   // ~71.7 KB
    cudaFuncSetAttribute(fused_kernel,
                         cudaFuncAttributeMaxDynamicSharedMemorySize, dyn_bytes);

    q_kernel<<<BB, UU>>>(dh, Wa, ba, bb);
    fused_kernel<<<2 * BB, 256, dyn_bytes>>>(E, Wb, Wv, bv, attn_out);
    combine_kernel<<<BB, ENC>>>(ctx_out);
    norm_kernel<<<BT / 256, 256>>>(attn_out);
}

// round 8
// speedup vs baseline: 2.3247x; 1.2615x over previous
#include <cuda_runtime.h>
#include <cuda_bf16.h>
#include <math.h>
#include <stdint.h>

// Problem dims
#define BB   64
#define TT   2048
#define ENC  512
#define DEC  512
#define UU   128
#define BT   (BB*TT)

// Tiling
#define STRIDE      36                  // floats per smem row (32 + 4 pad)
#define A_FLOATS    (128 * STRIDE)      // 4608 floats = 18432 B
#define STAGE_FLOATS (2 * A_FLOATS)     // A + B
#define STAGE_BYTES (STAGE_FLOATS * 4)  // 36864
#define DYN_BYTES   (2 * STAGE_BYTES + 1024)

#define NCHUNK 4                        // T-quarters per batch
#define NCTA   (BB * NCHUNK)            // 256 CTAs
#define ROWS_PER_CTA 512
#define TILES_PER_CTA 4

// scratch (__device__ globals per allocation-free rule)
__device__ float g_q[BB * UU];
__device__ float g_Wbt[UU * ENC];        // Wb transposed [n][k], tf32-rounded
__device__ float g_ctx_part[NCTA * ENC];
__device__ float g_l_part[NCTA];
__device__ float g_linv[BB];

// ---------------------------------------------------------------------------
// helpers
// ---------------------------------------------------------------------------
__device__ __forceinline__ uint32_t smem_u32(const void* p) {
    uint32_t a;
    asm("{ .reg .u64 t; cvta.to.shared.u64 t, %1; cvt.u32.u64 %0, t; }"
        : "=r"(a) : "l"(p));
    return a;
}
__device__ __forceinline__ float to_tf32(float f) {
    unsigned u; asm("cvt.rna.tf32.f32 %0, %1;" : "=r"(u) : "f"(f));
    return __uint_as_float(u);
}
__device__ __forceinline__ void cpy16(uint32_t dst, const void* src) {
    asm volatile("cp.async.cg.shared.global [%0], [%1], 16;"
                 :: "r"(dst), "l"(src) : "memory");
}
__device__ __forceinline__ void cp_commit() {
    asm volatile("cp.async.commit_group;" ::: "memory");
}
__device__ __forceinline__ void cp_wait1() {
    asm volatile("cp.async.wait_group 1;" ::: "memory");
}
__device__ __forceinline__ void cp_wait0() {
    asm volatile("cp.async.wait_group 0;" ::: "memory");
}
__device__ __forceinline__ float tanh_approx(float x) {
    float y; asm("tanh.approx.f32 %0, %1;" : "=f"(y) : "f"(x));
    return y;
}
__device__ __forceinline__ void mma_tf32(float& c0, float& c1, float& c2, float& c3,
                                         float a0, float a1, float a2, float a3,
                                         float b0, float b1) {
    asm volatile(
        "mma.sync.aligned.m16n8k8.row.col.f32.tf32.tf32.f32 "
        "{%0,%1,%2,%3}, {%4,%5,%6,%7}, {%8,%9}, {%0,%1,%2,%3};\n"
        : "+f"(c0), "+f"(c1), "+f"(c2), "+f"(c3)
        : "r"(__float_as_uint(a0)), "r"(__float_as_uint(a1)),
          "r"(__float_as_uint(a2)), "r"(__float_as_uint(a3)),
          "r"(__float_as_uint(b0)), "r"(__float_as_uint(b1)));
}

// ---------------------------------------------------------------------------
// K0a: q[b][u] = dh[b] @ Wa[:,u] + ba[u] + bb[u]
// ---------------------------------------------------------------------------
__global__ void q_kernel(const float* __restrict__ dh,
                         const float* __restrict__ Wa,
                         const float* __restrict__ ba,
                         const float* __restrict__ bb) {
    int b = blockIdx.x;
    int u = threadIdx.x;
    float acc = ba[u] + bb[u];
    const float* dhb = dh + b * DEC;
    #pragma unroll 8
    for (int e = 0; e < DEC; e++)
        acc = fmaf(dhb[e], Wa[e * UU + u], acc);
    g_q[b * UU + u] = acc;
}

// ---------------------------------------------------------------------------
// K0b: Wbt[n][k] = round_tf32(Wb[k][n])
// ---------------------------------------------------------------------------
__global__ void wbt_kernel(const float* __restrict__ Wb) {
    int i = blockIdx.x * 256 + threadIdx.x;    // 65536 total
    int k = i >> 7, n = i & 127;
    g_Wbt[n * ENC + k] = to_tf32(Wb[i]);
}

// ---------------------------------------------------------------------------
// K1 (fused): CTA = (b, quarter) -> 512 rows, 4 tiles of 128.
//   GEMM 128x128x512 per tile via mma.sync tf32, warp grid 2(M)x4(N),
//   double-buffered cp.async stages, fused tanh/exp epilogue + context.
// ---------------------------------------------------------------------------
extern __shared__ float dynsmem[];

__global__ void __launch_bounds__(256, 2)
fused_kernel(const float* __restrict__ E,
             const float* __restrict__ Wv,
             const float* __restrict__ bv,
             float* __restrict__ attn_out) {
    __shared__ float q_s[UU], wv_s[UU];
    __shared__ float p_tile[128];
    __shared__ float s_red[128][5];
    __shared__ float red[256];

    const int tid  = threadIdx.x;
    const int wid  = tid >> 5;
    const int lane = tid & 31;
    const int wm   = wid >> 2;           // 0..1  (M half)
    const int wn   = wid & 3;            // 0..3  (N quarter)
    const int b    = blockIdx.x >> 2;
    const int quarter = blockIdx.x & 3;
    const size_t rowbase = (size_t)b * TT + (size_t)quarter * ROWS_PER_CTA;

    const uint32_t dynb = (smem_u32(dynsmem) + 1023) & ~1023u;

    if (tid < UU) { q_s[tid] = g_q[b * UU + tid]; wv_s[tid] = Wv[tid]; }
    const float bv0 = bv[0];

    float2 ctx = make_float2(0.f, 0.f);
    float  l_acc = 0.f;

    // per-thread load mapping (both tiles: 128 rows x 32 k, 8 float4/row)
    const int lr = tid >> 1;                    // rows: 2 float4 per thread? no:
    // idx = tid + it*256, it 0..3 -> 1024 float4; r = idx>>3, q = idx&7
    // smem dst byte offset = r*144 + q*16

    // fragment smem offsets (floats)
    const int aoff = (wm * 64 + (lane >> 2)) * STRIDE + (lane & 3);
    const int boff = (wn * 32 + (lane >> 2)) * STRIDE + (lane & 3);

    for (int tile = 0; tile < TILES_PER_CTA; tile++) {
        const float* Ebt = E + (rowbase + (size_t)tile * 128) * ENC;

        float acc[4][4][4];
        #pragma unroll
        for (int mf = 0; mf < 4; mf++)
            #pragma unroll
            for (int nf = 0; nf < 4; nf++)
                { acc[mf][nf][0]=0.f; acc[mf][nf][1]=0.f;
                  acc[mf][nf][2]=0.f; acc[mf][nf][3]=0.f; }

        // ---- preload chunk 0 into stage 0
        {
            const uint32_t ab = dynb, bbs = dynb + A_FLOATS * 4;
            #pragma unroll
            for (int it = 0; it < 4; it++) {
                int idx = tid + it * 256;
                int r = idx >> 3, q = idx & 7;
                cpy16(ab  + r * 144 + q * 16, Ebt   + (size_t)r * ENC + q * 4);
                cpy16(bbs + r * 144 + q * 16, g_Wbt + (size_t)r * ENC + q * 4);
            }
            cp_commit();
        }

        for (int kt = 0; kt < 16; kt++) {
            // issue next chunk into other stage
            if (kt < 15) {
                const uint32_t sb = dynb + ((kt + 1) & 1) * STAGE_BYTES;
                const uint32_t ab = sb, bbs = sb + A_FLOATS * 4;
                const int k0 = (kt + 1) * 32;
                #pragma unroll
                for (int it = 0; it < 4; it++) {
                    int idx = tid + it * 256;
                    int r = idx >> 3, q = idx & 7;
                    cpy16(ab  + r * 144 + q * 16, Ebt   + (size_t)r * ENC + k0 + q * 4);
                    cpy16(bbs + r * 144 + q * 16, g_Wbt + (size_t)r * ENC + k0 + q * 4);
                }
                cp_commit();
                cp_wait1();
            } else {
                cp_wait0();
            }
            __syncthreads();

            const float* As = dynsmem + ((dynb - smem_u32(dynsmem)) >> 2)
                              + (kt & 1) * STAGE_FLOATS;
            const float* Bs = As + A_FLOATS;

            #pragma unroll
            for (int ks = 0; ks < 4; ks++) {
                const int kk = ks * 8;
                float a[4][4];
                #pragma unroll
                for (int mf = 0; mf < 4; mf++) {
                    const float* ap = As + aoff + mf * 16 * STRIDE + kk;
                    a[mf][0] = ap[0];
                    a[mf][1] = ap[8 * STRIDE];
                    a[mf][2] = ap[4];
                    a[mf][3] = ap[8 * STRIDE + 4];
                }
                float bf[4][2];
                #pragma unroll
                for (int nf = 0; nf < 4; nf++) {
                    const float* bp = Bs + boff + nf * 8 * STRIDE + kk;
                    bf[nf][0] = bp[0];
                    bf[nf][1] = bp[4];
                }
                #pragma unroll
                for (int mf = 0; mf < 4; mf++)
                    #pragma unroll
                    for (int nf = 0; nf < 4; nf++)
                        mma_tf32(acc[mf][nf][0], acc[mf][nf][1],
                                 acc[mf][nf][2], acc[mf][nf][3],
                                 a[mf][0], a[mf][1], a[mf][2], a[mf][3],
                                 bf[nf][0], bf[nf][1]);
            }
            __syncthreads();   // protect stage (kt&1) from next-iter overwrite
        }

        // ---- epilogue: s = Wv . tanh(q + k); per-thread covers 8 rows x 8 cols
        {
            const int u_lo = wn * 32 + 2 * (lane & 3);
            #pragma unroll
            for (int mf = 0; mf < 4; mf++) {
                #pragma unroll
                for (int h = 0; h < 2; h++) {
                    float ps = 0.f;
                    #pragma unroll
                    for (int nf = 0; nf < 4; nf++) {
                        const int u0 = u_lo + nf * 8;
                        ps = fmaf(wv_s[u0],
                                  tanh_approx(q_s[u0] + acc[mf][nf][2 * h]), ps);
                        ps = fmaf(wv_s[u0 + 1],
                                  tanh_approx(q_s[u0 + 1] + acc[mf][nf][2 * h + 1]), ps);
                    }
                    ps += __shfl_xor_sync(0xffffffffu, ps, 1);
                    ps += __shfl_xor_sync(0xffffffffu, ps, 2);
                    if ((lane & 3) == 0) {
                        const int row = wm * 64 + mf * 16 + (lane >> 2) + 8 * h;
                        s_red[row][wn] = ps;
                    }
                }
            }
        }
        __syncthreads();
        if (tid < 128) {
            const float s = s_red[tid][0] + s_red[tid][1]
                          + s_red[tid][2] + s_red[tid][3];
            const float p = __expf(s + bv0);
            p_tile[tid] = p;
            l_acc += p;
            attn_out[rowbase + (size_t)tile * 128 + tid] = p;
        }
        __syncthreads();

        // ---- context accumulation (E re-read, L2-hot)
        {
            const float2* E2 = (const float2*)Ebt;
            #pragma unroll 4
            for (int t = 0; t < 128; t++) {
                const float pt = p_tile[t];
                const float2 v = E2[(size_t)t * 256 + tid];
                ctx.x = fmaf(pt, v.x, ctx.x);
                ctx.y = fmaf(pt, v.y, ctx.y);
            }
        }
        __syncthreads();
    }

    // reduce l, write partials
    red[tid] = l_acc;
    __syncthreads();
    for (int off = 128; off > 0; off >>= 1) {
        if (tid < off) red[tid] += red[tid + off];
        __syncthreads();
    }
    if (tid == 0) g_l_part[blockIdx.x] = red[0];
    ((float2*)(g_ctx_part + (size_t)blockIdx.x * ENC))[tid] = ctx;
}

// ---------------------------------------------------------------------------
// K2: combine quarters -> normalized context + 1/l
// ---------------------------------------------------------------------------
__global__ void combine_kernel(float* __restrict__ ctx_out) {
    const int b = blockIdx.x;
    const int e = threadIdx.x;   // 512
    float l = 0.f, c = 0.f;
    #pragma unroll
    for (int qc = 0; qc < NCHUNK; qc++) {
        l += g_l_part[b * NCHUNK + qc];
        c += g_ctx_part[(size_t)(b * NCHUNK + qc) * ENC + e];
    }
    const float linv = 1.f / l;
    ctx_out[b * ENC + e] = c * linv;
    if (e == 0) g_linv[b] = linv;
}

// ---------------------------------------------------------------------------
// K3: normalize attn in place
// ---------------------------------------------------------------------------
__global__ void norm_kernel(float* __restrict__ attn) {
    const int i = blockIdx.x * blockDim.x + threadIdx.x;
    attn[i] *= g_linv[i >> 11];
}

// ---------------------------------------------------------------------------
extern "C" void kernel_launch(void* const* d_in, const int* in_sizes, int n_in,
                              void* d_out, int out_size) {
    const float* dh = (const float*)d_in[0];
    const float* E  = (const float*)d_in[1];
    const float* Wa = (const float*)d_in[2];
    const float* ba = (const float*)d_in[3];
    const float* Wb = (const float*)d_in[4];
    const float* bb = (const float*)d_in[5];
    const float* Wv = (const float*)d_in[6];
    const float* bv = (const float*)d_in[7];

    float* out      = (float*)d_out;
    float* ctx_out  = out;                 // [64,512]
    float* attn_out = out + BB * ENC;      // [64,2048]

    cudaFuncSetAttribute(fused_kernel,
                         cudaFuncAttributeMaxDynamicSharedMemorySize, DYN_BYTES);

    q_kernel<<<BB, UU>>>(dh, Wa, ba, bb);
    wbt_kernel<<<256, 256>>>(Wb);
    fused_kernel<<<NCTA, 256, DYN_BYTES>>>(E, Wv, bv, attn_out);
    combine_kernel<<<BB, ENC>>>(ctx_out);
    norm_kernel<<<BT / 256, 256>>>(attn_out);
}

// round 9
// speedup vs baseline: 2.5370x; 1.0913x over previous
#include <cuda_runtime.h>
#include <cuda_fp16.h>
#include <math.h>
#include <stdint.h>

// Problem dims
#define BB   64
#define TT   2048
#define ENC  512
#define DEC  512
#define UU   128
#define BT   (BB*TT)

// Tiling
#define ASTRIDE     36                   // fp32 per A smem row (32 + 4 pad)
#define A_FLOATS    (128 * ASTRIDE)      // 4608 floats = 18432 B
#define A_BYTES     (A_FLOATS * 4)
#define BSTRIDE_H   40                   // fp16 per B smem row (32 + 8 pad)
#define B_BYTES     (128 * BSTRIDE_H * 2)   // 10240
#define STAGE_BYTES (A_BYTES + B_BYTES)     // 28672 (28*1024)
#define STAGE_FLOATS (STAGE_BYTES / 4)
#define DYN_BYTES   (2 * STAGE_BYTES + 1024)

#define NCHUNK 4
#define NCTA   (BB * NCHUNK)             // 256 CTAs
#define ROWS_PER_CTA 512
#define TILES_PER_CTA 4

// scratch (__device__ globals per allocation-free rule)
__device__ float  g_q[BB * UU];
__device__ __half g_WbtH[UU * ENC];      // Wb transposed [n][k], fp16
__device__ float  g_ctx_part[NCTA * ENC];
__device__ float  g_l_part[NCTA];
__device__ float  g_linv[BB];

// ---------------------------------------------------------------------------
// helpers
// ---------------------------------------------------------------------------
__device__ __forceinline__ uint32_t smem_u32(const void* p) {
    uint32_t a;
    asm("{ .reg .u64 t; cvta.to.shared.u64 t, %1; cvt.u32.u64 %0, t; }"
        : "=r"(a) : "l"(p));
    return a;
}
__device__ __forceinline__ void cpy16(uint32_t dst, const void* src) {
    asm volatile("cp.async.cg.shared.global [%0], [%1], 16;"
                 :: "r"(dst), "l"(src) : "memory");
}
__device__ __forceinline__ void cp_commit() {
    asm volatile("cp.async.commit_group;" ::: "memory");
}
__device__ __forceinline__ void cp_wait1() {
    asm volatile("cp.async.wait_group 1;" ::: "memory");
}
__device__ __forceinline__ void cp_wait0() {
    asm volatile("cp.async.wait_group 0;" ::: "memory");
}
__device__ __forceinline__ float tanh_approx(float x) {
    float y; asm("tanh.approx.f32 %0, %1;" : "=f"(y) : "f"(x));
    return y;
}
__device__ __forceinline__ uint32_t packh2(float lo, float hi) {
    __half2 h = __float22half2_rn(make_float2(lo, hi));
    return *(uint32_t*)&h;
}
__device__ __forceinline__ void mma_f16(float* c, const uint32_t* a,
                                        const uint32_t* b) {
    asm volatile(
        "mma.sync.aligned.m16n8k16.row.col.f32.f16.f16.f32 "
        "{%0,%1,%2,%3}, {%4,%5,%6,%7}, {%8,%9}, {%0,%1,%2,%3};\n"
        : "+f"(c[0]), "+f"(c[1]), "+f"(c[2]), "+f"(c[3])
        : "r"(a[0]), "r"(a[1]), "r"(a[2]), "r"(a[3]),
          "r"(b[0]), "r"(b[1]));
}

// ---------------------------------------------------------------------------
// K0a: q[b][u] = dh[b] @ Wa[:,u] + ba[u] + bb[u]
// ---------------------------------------------------------------------------
__global__ void q_kernel(const float* __restrict__ dh,
                         const float* __restrict__ Wa,
                         const float* __restrict__ ba,
                         const float* __restrict__ bb) {
    int b = blockIdx.x;
    int u = threadIdx.x;
    float acc = ba[u] + bb[u];
    const float* dhb = dh + b * DEC;
    #pragma unroll 8
    for (int e = 0; e < DEC; e++)
        acc = fmaf(dhb[e], Wa[e * UU + u], acc);
    g_q[b * UU + u] = acc;
}

// ---------------------------------------------------------------------------
// K0b: WbtH[n][k] = fp16(Wb[k][n])
// ---------------------------------------------------------------------------
__global__ void wbt_kernel(const float* __restrict__ Wb) {
    int i = blockIdx.x * 256 + threadIdx.x;    // 65536 total
    int k = i >> 7, n = i & 127;
    g_WbtH[n * ENC + k] = __float2half_rn(Wb[i]);
}

// ---------------------------------------------------------------------------
// K1 (fused): CTA = (b, quarter) -> 512 rows, 4 tiles of 128.
//   GEMM 128x128x512 per tile via mma.sync fp16 k16, warp grid 4(M)x2(N),
//   A fp32 in smem (cp.async) converted in-register; B fp16 in smem.
// ---------------------------------------------------------------------------
extern __shared__ float dynsmem[];

__global__ void __launch_bounds__(256, 2)
fused_kernel(const float* __restrict__ E,
             const float* __restrict__ Wv,
             const float* __restrict__ bv,
             float* __restrict__ attn_out) {
    __shared__ float q_s[UU], wv_s[UU];
    __shared__ float p_tile[128];
    __shared__ float s_red[128][3];      // [row][wn] (pad to 3)
    __shared__ float red[256];

    const int tid  = threadIdx.x;
    const int wid  = tid >> 5;
    const int lane = tid & 31;
    const int wm   = wid >> 1;           // 0..3  (M quarter: 32 rows)
    const int wn   = wid & 1;            // 0..1  (N half: 64 cols)
    const int b    = blockIdx.x >> 2;
    const int quarter = blockIdx.x & 3;
    const size_t rowbase = (size_t)b * TT + (size_t)quarter * ROWS_PER_CTA;

    const uint32_t dynb = (smem_u32(dynsmem) + 1023) & ~1023u;
    const int dynoff = (int)(dynb - smem_u32(dynsmem)) >> 2;   // float offset

    if (tid < UU) { q_s[tid] = g_q[b * UU + tid]; wv_s[tid] = Wv[tid]; }
    const float bv0 = bv[0];

    float2 ctx = make_float2(0.f, 0.f);
    float  l_acc = 0.f;

    for (int tile = 0; tile < TILES_PER_CTA; tile++) {
        const float* Ebt = E + (rowbase + (size_t)tile * 128) * ENC;

        float acc[2][8][4];              // [mf][nf][frag]
        #pragma unroll
        for (int mf = 0; mf < 2; mf++)
            #pragma unroll
            for (int nf = 0; nf < 8; nf++)
                { acc[mf][nf][0]=0.f; acc[mf][nf][1]=0.f;
                  acc[mf][nf][2]=0.f; acc[mf][nf][3]=0.f; }

        // ---- preload chunk 0 into stage 0
        {
            const uint32_t ab = dynb, bbs = dynb + A_BYTES;
            #pragma unroll
            for (int it = 0; it < 4; it++) {
                int idx = tid + it * 256;
                int r = idx >> 3, q = idx & 7;
                cpy16(ab + r * 144 + q * 16, Ebt + (size_t)r * ENC + q * 4);
            }
            #pragma unroll
            for (int it = 0; it < 2; it++) {
                int idx = tid + it * 256;
                int n = idx >> 2, q = idx & 3;
                cpy16(bbs + n * 80 + q * 16, g_WbtH + (size_t)n * ENC + q * 8);
            }
            cp_commit();
        }

        for (int kt = 0; kt < 16; kt++) {
            if (kt < 15) {
                const uint32_t sb = dynb + ((kt + 1) & 1) * STAGE_BYTES;
                const uint32_t ab = sb, bbs = sb + A_BYTES;
                const int k0 = (kt + 1) * 32;
                #pragma unroll
                for (int it = 0; it < 4; it++) {
                    int idx = tid + it * 256;
                    int r = idx >> 3, q = idx & 7;
                    cpy16(ab + r * 144 + q * 16,
                          Ebt + (size_t)r * ENC + k0 + q * 4);
                }
                #pragma unroll
                for (int it = 0; it < 2; it++) {
                    int idx = tid + it * 256;
                    int n = idx >> 2, q = idx & 3;
                    cpy16(bbs + n * 80 + q * 16,
                          g_WbtH + (size_t)n * ENC + k0 + q * 8);
                }
                cp_commit();
                cp_wait1();
            } else {
                cp_wait0();
            }
            __syncthreads();

            const float* As = dynsmem + dynoff + (kt & 1) * STAGE_FLOATS;
            const __half* Bs = (const __half*)(As + A_FLOATS);

            #pragma unroll
            for (int ks = 0; ks < 2; ks++) {
                const int kk = ks * 16;
                // A fragments (fp32 smem -> fp16 regs)
                uint32_t af[2][4];
                #pragma unroll
                for (int mf = 0; mf < 2; mf++) {
                    const float* ap = As
                        + (wm * 32 + mf * 16 + (lane >> 2)) * ASTRIDE
                        + kk + (lane & 3) * 2;
                    float2 v0 = *(const float2*)(ap);
                    float2 v1 = *(const float2*)(ap + 8 * ASTRIDE);
                    float2 v2 = *(const float2*)(ap + 8);
                    float2 v3 = *(const float2*)(ap + 8 * ASTRIDE + 8);
                    af[mf][0] = packh2(v0.x, v0.y);
                    af[mf][1] = packh2(v1.x, v1.y);
                    af[mf][2] = packh2(v2.x, v2.y);
                    af[mf][3] = packh2(v3.x, v3.y);
                }
                // B fragments (fp16 smem direct)
                uint32_t bf[8][2];
                #pragma unroll
                for (int nf = 0; nf < 8; nf++) {
                    const __half* bp = Bs
                        + (wn * 64 + nf * 8 + (lane >> 2)) * BSTRIDE_H
                        + kk + (lane & 3) * 2;
                    bf[nf][0] = *(const uint32_t*)(bp);
                    bf[nf][1] = *(const uint32_t*)(bp + 8);
                }
                #pragma unroll
                for (int mf = 0; mf < 2; mf++)
                    #pragma unroll
                    for (int nf = 0; nf < 8; nf++)
                        mma_f16(acc[mf][nf], af[mf], bf[nf]);
            }
            __syncthreads();   // protect stage (kt&1) from next-iter overwrite
        }

        // ---- epilogue: s = Wv . tanh(q + k)
        {
            #pragma unroll
            for (int mf = 0; mf < 2; mf++) {
                #pragma unroll
                for (int h = 0; h < 2; h++) {
                    float ps = 0.f;
                    #pragma unroll
                    for (int nf = 0; nf < 8; nf++) {
                        const int u0 = wn * 64 + nf * 8 + 2 * (lane & 3);
                        ps = fmaf(wv_s[u0],
                                  tanh_approx(q_s[u0] + acc[mf][nf][2 * h]), ps);
                        ps = fmaf(wv_s[u0 + 1],
                                  tanh_approx(q_s[u0 + 1] + acc[mf][nf][2 * h + 1]), ps);
                    }
                    ps += __shfl_xor_sync(0xffffffffu, ps, 1);
                    ps += __shfl_xor_sync(0xffffffffu, ps, 2);
                    if ((lane & 3) == 0) {
                        const int row = wm * 32 + mf * 16 + (lane >> 2) + 8 * h;
                        s_red[row][wn] = ps;
                    }
                }
            }
        }
        __syncthreads();
        if (tid < 128) {
            const float s = s_red[tid][0] + s_red[tid][1];
            const float p = __expf(s + bv0);
            p_tile[tid] = p;
            l_acc += p;
            attn_out[rowbase + (size_t)tile * 128 + tid] = p;
        }
        __syncthreads();

        // ---- context accumulation (E re-read, L2-hot)
        {
            const float2* E2 = (const float2*)Ebt;
            #pragma unroll 4
            for (int t = 0; t < 128; t++) {
                const float pt = p_tile[t];
                const float2 v = E2[(size_t)t * 256 + tid];
                ctx.x = fmaf(pt, v.x, ctx.x);
                ctx.y = fmaf(pt, v.y, ctx.y);
            }
        }
        __syncthreads();
    }

    // reduce l, write partials
    red[tid] = l_acc;
    __syncthreads();
    for (int off = 128; off > 0; off >>= 1) {
        if (tid < off) red[tid] += red[tid + off];
        __syncthreads();
    }
    if (tid == 0) g_l_part[blockIdx.x] = red[0];
    ((float2*)(g_ctx_part + (size_t)blockIdx.x * ENC))[tid] = ctx;
}

// ---------------------------------------------------------------------------
// K2: combine quarters -> normalized context + 1/l
// ---------------------------------------------------------------------------
__global__ void combine_kernel(float* __restrict__ ctx_out) {
    const int b = blockIdx.x;
    const int e = threadIdx.x;   // 512
    float l = 0.f, c = 0.f;
    #pragma unroll
    for (int qc = 0; qc < NCHUNK; qc++) {
        l += g_l_part[b * NCHUNK + qc];
        c += g_ctx_part[(size_t)(b * NCHUNK + qc) * ENC + e];
    }
    const float linv = 1.f / l;
    ctx_out[b * ENC + e] = c * linv;
    if (e == 0) g_linv[b] = linv;
}

// ---------------------------------------------------------------------------
// K3: normalize attn in place
// ---------------------------------------------------------------------------
__global__ void norm_kernel(float* __restrict__ attn) {
    const int i = blockIdx.x * blockDim.x + threadIdx.x;
    attn[i] *= g_linv[i >> 11];
}

// ---------------------------------------------------------------------------
extern "C" void kernel_launch(void* const* d_in, const int* in_sizes, int n_in,
                              void* d_out, int out_size) {
    const float* dh = (const float*)d_in[0];
    const float* E  = (const float*)d_in[1];
    const float* Wa = (const float*)d_in[2];
    const float* ba = (const float*)d_in[3];
    const float* Wb = (const float*)d_in[4];
    const float* bb = (const float*)d_in[5];
    const float* Wv = (const float*)d_in[6];
    const float* bv = (const float*)d_in[7];

    float* out      = (float*)d_out;
    float* ctx_out  = out;                 // [64,512]
    float* attn_out = out + BB * ENC;      // [64,2048]

    cudaFuncSetAttribute(fused_kernel,
                         cudaFuncAttributeMaxDynamicSharedMemorySize, DYN_BYTES);

    q_kernel<<<BB, UU>>>(dh, Wa, ba, bb);
    wbt_kernel<<<256, 256>>>(Wb);
    fused_kernel<<<NCTA, 256, DYN_BYTES>>>(E, Wv, bv, attn_out);
    combine_kernel<<<BB, ENC>>>(ctx_out);
    norm_kernel<<<BT / 256, 256>>>(attn_out);
}

// round 10
// speedup vs baseline: 2.7959x; 1.1021x over previous
#include <cuda_runtime.h>
#include <cuda_fp16.h>
#include <math.h>
#include <stdint.h>

// Problem dims
#define BB   64
#define TT   2048
#define ENC  512
#define DEC  512
#define UU   128
#define BT   (BB*TT)

// Tiling
#define ASTRIDE     40                    // fp32 per A smem row (32 + 8 pad) — conflict-free
#define A_BYTES     (128 * ASTRIDE * 4)   // 20480
#define A_FLOATS    (128 * ASTRIDE)
#define BSTRIDE_H   40                    // fp16 per B smem row — conflict-free
#define B_BYTES     (128 * BSTRIDE_H * 2) // 10240
#define STAGE_BYTES (A_BYTES + B_BYTES)   // 30720 (30 KB, 1KB-aligned)
#define STAGE_FLOATS (STAGE_BYTES / 4)
#define NSTAGE      3
#define DYN_BYTES   (NSTAGE * STAGE_BYTES + 1024)

#define NCHUNK 4
#define NCTA   (BB * NCHUNK)              // 256 CTAs
#define ROWS_PER_CTA 512
#define TILES_PER_CTA 4
#define NCHUNKS_TOTAL (TILES_PER_CTA * 16)   // 64

// scratch (__device__ globals per allocation-free rule)
__device__ float  g_q[BB * UU];
__device__ __half g_WbtH[UU * ENC];       // Wb transposed [n][k], fp16
__device__ float  g_ctx_part[NCTA * ENC];
__device__ float  g_l_part[NCTA];

// ---------------------------------------------------------------------------
// helpers
// ---------------------------------------------------------------------------
__device__ __forceinline__ uint32_t smem_u32(const void* p) {
    uint32_t a;
    asm("{ .reg .u64 t; cvta.to.shared.u64 t, %1; cvt.u32.u64 %0, t; }"
        : "=r"(a) : "l"(p));
    return a;
}
__device__ __forceinline__ void cpy16(uint32_t dst, const void* src) {
    asm volatile("cp.async.cg.shared.global [%0], [%1], 16;"
                 :: "r"(dst), "l"(src) : "memory");
}
__device__ __forceinline__ void cp_commit() {
    asm volatile("cp.async.commit_group;" ::: "memory");
}
__device__ __forceinline__ void cp_wait1() {
    asm volatile("cp.async.wait_group 1;" ::: "memory");
}
__device__ __forceinline__ float tanh_approx(float x) {
    float y; asm("tanh.approx.f32 %0, %1;" : "=f"(y) : "f"(x));
    return y;
}
__device__ __forceinline__ uint32_t packh2(float lo, float hi) {
    __half2 h = __float22half2_rn(make_float2(lo, hi));
    return *(uint32_t*)&h;
}
__device__ __forceinline__ void mma_f16(float* c, const uint32_t* a,
                                        const uint32_t* b) {
    asm volatile(
        "mma.sync.aligned.m16n8k16.row.col.f32.f16.f16.f32 "
        "{%0,%1,%2,%3}, {%4,%5,%6,%7}, {%8,%9}, {%0,%1,%2,%3};\n"
        : "+f"(c[0]), "+f"(c[1]), "+f"(c[2]), "+f"(c[3])
        : "r"(a[0]), "r"(a[1]), "r"(a[2]), "r"(a[3]),
          "r"(b[0]), "r"(b[1]));
}

// ---------------------------------------------------------------------------
// K0: prep. Blocks 0..31: q = dh@Wa + ba + bb (2 batches/block).
//          Blocks 32..287: WbtH[n][k] = fp16(Wb[k][n]).
// ---------------------------------------------------------------------------
__global__ void prep_kernel(const float* __restrict__ dh,
                            const float* __restrict__ Wa,
                            const float* __restrict__ ba,
                            const float* __restrict__ bb,
                            const float* __restrict__ Wb) {
    if (blockIdx.x < 32) {
        const int b = blockIdx.x * 2 + (threadIdx.x >> 7);
        const int u = threadIdx.x & 127;
        float acc = ba[u] + bb[u];
        const float* dhb = dh + b * DEC;
        #pragma unroll 8
        for (int e = 0; e < DEC; e++)
            acc = fmaf(dhb[e], Wa[e * UU + u], acc);
        g_q[b * UU + u] = acc;
    } else {
        const int i = (blockIdx.x - 32) * 256 + threadIdx.x;   // 65536 total
        const int k = i >> 7, n = i & 127;
        g_WbtH[n * ENC + k] = __float2half_rn(Wb[i]);
    }
}

// ---------------------------------------------------------------------------
// K1 (fused): CTA = (b, quarter) -> 512 rows, 4 tiles of 128.
//   Continuous 3-stage cp.async pipeline across all 64 K-chunks,
//   mma.sync fp16 k16 (warp grid 4Mx2N), fused tanh/exp epilogue + context.
// ---------------------------------------------------------------------------
extern __shared__ float dynsmem[];

__global__ void __launch_bounds__(256, 2)
fused_kernel(const float* __restrict__ E,
             const float* __restrict__ Wv,
             const float* __restrict__ bv,
             float* __restrict__ attn_out) {
    __shared__ float q_s[UU], wv_s[UU];
    __shared__ float p_tile[128];
    __shared__ float s_red[128][3];
    __shared__ float red[256];

    const int tid  = threadIdx.x;
    const int lane = tid & 31;
    const int wid  = tid >> 5;
    const int wm   = wid >> 1;           // 0..3  (M quarter: 32 rows)
    const int wn   = wid & 1;            // 0..1  (N half: 64 cols)
    const int b    = blockIdx.x >> 2;
    const int quarter = blockIdx.x & 3;
    const size_t rowbase = (size_t)b * TT + (size_t)quarter * ROWS_PER_CTA;

    const uint32_t dynb = (smem_u32(dynsmem) + 1023) & ~1023u;
    const int dynoff = (int)(dynb - smem_u32(dynsmem)) >> 2;

    if (tid < UU) { q_s[tid] = g_q[b * UU + tid]; wv_s[tid] = Wv[tid]; }
    const float bv0 = bv[0];

    float2 ctx = make_float2(0.f, 0.f);
    float  l_acc = 0.f;

    // chunk loader: c = tile*16 + kt
    auto load_chunk = [&](int c) {
        const int tile = c >> 4, kt = c & 15;
        const uint32_t sb = dynb + (c % NSTAGE) * STAGE_BYTES;
        const uint32_t bbs = sb + A_BYTES;
        const float*  Asrc = E + (rowbase + (size_t)tile * 128) * ENC + kt * 32;
        const __half* Bsrc = g_WbtH + kt * 32;
        #pragma unroll
        for (int it = 0; it < 4; it++) {
            int idx = tid + it * 256;
            int r = idx >> 3, q = idx & 7;
            cpy16(sb + r * 160 + q * 16, Asrc + (size_t)r * ENC + q * 4);
        }
        #pragma unroll
        for (int it = 0; it < 2; it++) {
            int idx = tid + it * 256;
            int n = idx >> 2, q = idx & 3;
            cpy16(bbs + n * 80 + q * 16, Bsrc + (size_t)n * ENC + q * 8);
        }
        cp_commit();
    };

    // prologue: chunks 0, 1
    load_chunk(0);
    load_chunk(1);

    float acc[2][8][4];
    #pragma unroll
    for (int mf = 0; mf < 2; mf++)
        #pragma unroll
        for (int nf = 0; nf < 8; nf++)
            { acc[mf][nf][0]=0.f; acc[mf][nf][1]=0.f;
              acc[mf][nf][2]=0.f; acc[mf][nf][3]=0.f; }

    for (int c = 0; c < NCHUNKS_TOTAL; c++) {
        cp_wait1();            // chunk c resident (in-order group completion)
        __syncthreads();       // all warps done with stage (c-1)%3 LDS
        if (c + 2 < NCHUNKS_TOTAL) load_chunk(c + 2);
        else                       cp_commit();       // keep group count uniform

        const float*  As = dynsmem + dynoff + (c % NSTAGE) * STAGE_FLOATS;
        const __half* Bs = (const __half*)(As + A_FLOATS);

        #pragma unroll
        for (int ks = 0; ks < 2; ks++) {
            const int kk = ks * 16;
            uint32_t af[2][4];
            #pragma unroll
            for (int mf = 0; mf < 2; mf++) {
                const float* ap = As
                    + (wm * 32 + mf * 16 + (lane >> 2)) * ASTRIDE
                    + kk + (lane & 3) * 2;
                float2 v0 = *(const float2*)(ap);
                float2 v1 = *(const float2*)(ap + 8 * ASTRIDE);
                float2 v2 = *(const float2*)(ap + 8);
                float2 v3 = *(const float2*)(ap + 8 * ASTRIDE + 8);
                af[mf][0] = packh2(v0.x, v0.y);
                af[mf][1] = packh2(v1.x, v1.y);
                af[mf][2] = packh2(v2.x, v2.y);
                af[mf][3] = packh2(v3.x, v3.y);
            }
            uint32_t bf[8][2];
            #pragma unroll
            for (int nf = 0; nf < 8; nf++) {
                const __half* bp = Bs
                    + (wn * 64 + nf * 8 + (lane >> 2)) * BSTRIDE_H
                    + kk + (lane & 3) * 2;
                bf[nf][0] = *(const uint32_t*)(bp);
                bf[nf][1] = *(const uint32_t*)(bp + 8);
            }
            #pragma unroll
            for (int mf = 0; mf < 2; mf++)
                #pragma unroll
                for (int nf = 0; nf < 8; nf++)
                    mma_f16(acc[mf][nf], af[mf], bf[nf]);
        }

        if ((c & 15) != 15) continue;

        // ================= tile epilogue (tile = c >> 4) =================
        const int tile = c >> 4;
        const float* Ebt = E + (rowbase + (size_t)tile * 128) * ENC;

        #pragma unroll
        for (int mf = 0; mf < 2; mf++) {
            #pragma unroll
            for (int h = 0; h < 2; h++) {
                float ps = 0.f;
                #pragma unroll
                for (int nf = 0; nf < 8; nf++) {
                    const int u0 = wn * 64 + nf * 8 + 2 * (lane & 3);
                    ps = fmaf(wv_s[u0],
                              tanh_approx(q_s[u0] + acc[mf][nf][2 * h]), ps);
                    ps = fmaf(wv_s[u0 + 1],
                              tanh_approx(q_s[u0 + 1] + acc[mf][nf][2 * h + 1]), ps);
                }
                ps += __shfl_xor_sync(0xffffffffu, ps, 1);
                ps += __shfl_xor_sync(0xffffffffu, ps, 2);
                if ((lane & 3) == 0) {
                    const int row = wm * 32 + mf * 16 + (lane >> 2) + 8 * h;
                    s_red[row][wn] = ps;
                }
            }
        }
        // reset accumulators for next tile
        #pragma unroll
        for (int mf = 0; mf < 2; mf++)
            #pragma unroll
            for (int nf = 0; nf < 8; nf++)
                { acc[mf][nf][0]=0.f; acc[mf][nf][1]=0.f;
                  acc[mf][nf][2]=0.f; acc[mf][nf][3]=0.f; }
        __syncthreads();
        if (tid < 128) {
            const float s = s_red[tid][0] + s_red[tid][1];
            const float p = __expf(s + bv0);
            p_tile[tid] = p;
            l_acc += p;
            attn_out[rowbase + (size_t)tile * 128 + tid] = p;
        }
        __syncthreads();

        // context accumulation (E re-read, L2-hot; overlaps in-flight cp.async)
        {
            const float2* E2 = (const float2*)Ebt;
            #pragma unroll 4
            for (int t = 0; t < 128; t++) {
                const float pt = p_tile[t];
                const float2 v = E2[(size_t)t * 256 + tid];
                ctx.x = fmaf(pt, v.x, ctx.x);
                ctx.y = fmaf(pt, v.y, ctx.y);
            }
        }
        __syncthreads();
    }

    // reduce l, write partials
    red[tid] = l_acc;
    __syncthreads();
    for (int off = 128; off > 0; off >>= 1) {
        if (tid < off) red[tid] += red[tid + off];
        __syncthreads();
    }
    if (tid == 0) g_l_part[blockIdx.x] = red[0];
    ((float2*)(g_ctx_part + (size_t)blockIdx.x * ENC))[tid] = ctx;
}

// ---------------------------------------------------------------------------
// K2: combine quarters -> normalized context; normalize attn in place.
// ---------------------------------------------------------------------------
__global__ void combine_norm_kernel(float* __restrict__ ctx_out,
                                    float* __restrict__ attn) {
    const int b = blockIdx.x;
    const int e = threadIdx.x;   // 512
    float l = 0.f, c = 0.f;
    #pragma unroll
    for (int qc = 0; qc < NCHUNK; qc++) {
        l += g_l_part[b * NCHUNK + qc];
        c += g_ctx_part[(size_t)(b * NCHUNK + qc) * ENC + e];
    }
    const float linv = 1.f / l;
    ctx_out[b * ENC + e] = c * linv;
    float* ab = attn + (size_t)b * TT;
    #pragma unroll
    for (int i = 0; i < TT / 512; i++)
        ab[e + i * 512] *= linv;
}

// ---------------------------------------------------------------------------
extern "C" void kernel_launch(void* const* d_in, const int* in_sizes, int n_in,
                              void* d_out, int out_size) {
    const float* dh = (const float*)d_in[0];
    const float* E  = (const float*)d_in[1];
    const float* Wa = (const float*)d_in[2];
    const float* ba = (const float*)d_in[3];
    const float* Wb = (const float*)d_in[4];
    const float* bb = (const float*)d_in[5];
    const float* Wv = (const float*)d_in[6];
    const float* bv = (const float*)d_in[7];

    float* out      = (float*)d_out;
    float* ctx_out  = out;                 // [64,512]
    float* attn_out = out + BB * ENC;      // [64,2048]

    cudaFuncSetAttribute(fused_kernel,
                         cudaFuncAttributeMaxDynamicSharedMemorySize, DYN_BYTES);

    prep_kernel<<<288, 256>>>(dh, Wa, ba, bb, Wb);
    fused_kernel<<<NCTA, 256, DYN_BYTES>>>(E, Wv, bv, attn_out);
    combine_norm_kernel<<<BB, ENC>>>(ctx_out, attn_out);
}

// round 11
// speedup vs baseline: 3.1935x; 1.1422x over previous
#include <cuda_runtime.h>
#include <cuda_fp16.h>
#include <math.h>
#include <stdint.h>

// Problem dims
#define BB   64
#define TT   2048
#define ENC  512
#define DEC  512
#define UU   128
#define BT   (BB*TT)

// Tiling
#define ASTRIDE     40                    // fp32 per A smem row (32 + 8 pad) — conflict-free
#define A_BYTES     (128 * ASTRIDE * 4)   // 20480
#define A_FLOATS    (128 * ASTRIDE)
#define BSTRIDE_H   40                    // fp16 per B smem row — conflict-free
#define B_BYTES     (128 * BSTRIDE_H * 2) // 10240
#define STAGE_BYTES (A_BYTES + B_BYTES)   // 30720
#define STAGE_FLOATS (STAGE_BYTES / 4)
#define NSTAGE      3
#define DYN_BYTES   (NSTAGE * STAGE_BYTES + 1024)

#define NCHUNK 4
#define NCTA   (BB * NCHUNK)              // 256 CTAs
#define ROWS_PER_CTA 512
#define TILES_PER_CTA 4
#define NCHUNKS_TOTAL (TILES_PER_CTA * 16)   // 64

// scratch (__device__ globals per allocation-free rule)
__device__ float  g_q[BB * UU];
__device__ __half g_WbtH[UU * ENC];       // Wb transposed [n][k], fp16
__device__ float  g_ctx_part[NCTA * ENC];
__device__ float  g_l_part[NCTA];

// ---------------------------------------------------------------------------
// helpers
// ---------------------------------------------------------------------------
__device__ __forceinline__ uint32_t smem_u32(const void* p) {
    uint32_t a;
    asm("{ .reg .u64 t; cvta.to.shared.u64 t, %1; cvt.u32.u64 %0, t; }"
        : "=r"(a) : "l"(p));
    return a;
}
__device__ __forceinline__ void cpy16(uint32_t dst, const void* src) {
    asm volatile("cp.async.cg.shared.global [%0], [%1], 16;"
                 :: "r"(dst), "l"(src) : "memory");
}
__device__ __forceinline__ void cp_commit() {
    asm volatile("cp.async.commit_group;" ::: "memory");
}
__device__ __forceinline__ void cp_wait1() {
    asm volatile("cp.async.wait_group 1;" ::: "memory");
}
__device__ __forceinline__ float tanh_approx(float x) {
    float y; asm("tanh.approx.f32 %0, %1;" : "=f"(y) : "f"(x));
    return y;
}
__device__ __forceinline__ uint32_t packh2(float lo, float hi) {
    __half2 h = __float22half2_rn(make_float2(lo, hi));
    return *(uint32_t*)&h;
}
__device__ __forceinline__ void mma_f16(float* c, const uint32_t* a,
                                        const uint32_t* b) {
    asm volatile(
        "mma.sync.aligned.m16n8k16.row.col.f32.f16.f16.f32 "
        "{%0,%1,%2,%3}, {%4,%5,%6,%7}, {%8,%9}, {%0,%1,%2,%3};\n"
        : "+f"(c[0]), "+f"(c[1]), "+f"(c[2]), "+f"(c[3])
        : "r"(a[0]), "r"(a[1]), "r"(a[2]), "r"(a[3]),
          "r"(b[0]), "r"(b[1]));
}

// ---------------------------------------------------------------------------
// K0: prep, 512 threads/block.
//   Blocks 0..63:    q[b][u] — e-dim split 4-way, smem reduce.
//   Blocks 64..191:  WbtH[n][k] = fp16(Wb[k][n]), 512 elems/block... (65536/512=128 blocks)
// ---------------------------------------------------------------------------
__global__ void prep_kernel(const float* __restrict__ dh,
                            const float* __restrict__ Wa,
                            const float* __restrict__ ba,
                            const float* __restrict__ bb,
                            const float* __restrict__ Wb) {
    if (blockIdx.x < BB) {
        __shared__ float part[512];
        const int b  = blockIdx.x;
        const int u  = threadIdx.x & 127;
        const int eg = threadIdx.x >> 7;          // e-quarter 0..3
        float acc = 0.f;
        const float* dhb = dh + b * DEC + eg * 128;
        const float* wap = Wa + (size_t)(eg * 128) * UU + u;
        #pragma unroll 16
        for (int e = 0; e < 128; e++)
            acc = fmaf(dhb[e], wap[(size_t)e * UU], acc);
        part[threadIdx.x] = acc;
        __syncthreads();
        if (threadIdx.x < 128) {
            const float q = part[threadIdx.x] + part[threadIdx.x + 128]
                          + part[threadIdx.x + 256] + part[threadIdx.x + 384]
                          + ba[u] + bb[u];
            g_q[b * UU + u] = q;
        }
    } else {
        const int i = (blockIdx.x - BB) * 512 + threadIdx.x;   // 65536 total
        const int k = i >> 7, n = i & 127;
        g_WbtH[n * ENC + k] = __float2half_rn(Wb[i]);
    }
}

// ---------------------------------------------------------------------------
// K1 (fused): CTA = (b, quarter) -> 512 rows, 4 tiles of 128.
//   Continuous 3-stage cp.async pipeline across all 64 K-chunks,
//   mma.sync fp16 k16 (warp grid 4Mx2N), fused tanh/exp epilogue + context.
// ---------------------------------------------------------------------------
extern __shared__ float dynsmem[];

__global__ void __launch_bounds__(256, 2)
fused_kernel(const float* __restrict__ E,
             const float* __restrict__ Wv,
             const float* __restrict__ bv,
             float* __restrict__ attn_out) {
    __shared__ float q_s[UU], wv_s[UU];
    __shared__ float p_tile[128];
    __shared__ float s_red[128][3];
    __shared__ float red[256];

    const int tid  = threadIdx.x;
    const int lane = tid & 31;
    const int wid  = tid >> 5;
    const int wm   = wid >> 1;           // 0..3  (M quarter: 32 rows)
    const int wn   = wid & 1;            // 0..1  (N half: 64 cols)
    const int b    = blockIdx.x >> 2;
    const int quarter = blockIdx.x & 3;
    const size_t rowbase = (size_t)b * TT + (size_t)quarter * ROWS_PER_CTA;

    const uint32_t dynb = (smem_u32(dynsmem) + 1023) & ~1023u;
    const int dynoff = (int)(dynb - smem_u32(dynsmem)) >> 2;

    if (tid < UU) { q_s[tid] = g_q[b * UU + tid]; wv_s[tid] = Wv[tid]; }
    const float bv0 = bv[0];

    float2 ctx = make_float2(0.f, 0.f);
    float  l_acc = 0.f;

    // chunk loader: c = tile*16 + kt
    auto load_chunk = [&](int c) {
        const int tile = c >> 4, kt = c & 15;
        const uint32_t sb = dynb + (c % NSTAGE) * STAGE_BYTES;
        const uint32_t bbs = sb + A_BYTES;
        const float*  Asrc = E + (rowbase + (size_t)tile * 128) * ENC + kt * 32;
        const __half* Bsrc = g_WbtH + kt * 32;
        #pragma unroll
        for (int it = 0; it < 4; it++) {
            int idx = tid + it * 256;
            int r = idx >> 3, q = idx & 7;
            cpy16(sb + r * 160 + q * 16, Asrc + (size_t)r * ENC + q * 4);
        }
        #pragma unroll
        for (int it = 0; it < 2; it++) {
            int idx = tid + it * 256;
            int n = idx >> 2, q = idx & 3;
            cpy16(bbs + n * 80 + q * 16, Bsrc + (size_t)n * ENC + q * 8);
        }
        cp_commit();
    };

    // prologue: chunks 0, 1
    load_chunk(0);
    load_chunk(1);

    float acc[2][8][4];
    #pragma unroll
    for (int mf = 0; mf < 2; mf++)
        #pragma unroll
        for (int nf = 0; nf < 8; nf++)
            { acc[mf][nf][0]=0.f; acc[mf][nf][1]=0.f;
              acc[mf][nf][2]=0.f; acc[mf][nf][3]=0.f; }

    for (int c = 0; c < NCHUNKS_TOTAL; c++) {
        cp_wait1();            // chunk c resident (in-order group completion)
        __syncthreads();       // all warps done with stage (c-1)%3 LDS
        if (c + 2 < NCHUNKS_TOTAL) load_chunk(c + 2);
        else                       cp_commit();       // keep group count uniform

        const float*  As = dynsmem + dynoff + (c % NSTAGE) * STAGE_FLOATS;
        const __half* Bs = (const __half*)(As + A_FLOATS);

        #pragma unroll
        for (int ks = 0; ks < 2; ks++) {
            const int kk = ks * 16;
            uint32_t af[2][4];
            #pragma unroll
            for (int mf = 0; mf < 2; mf++) {
                const float* ap = As
                    + (wm * 32 + mf * 16 + (lane >> 2)) * ASTRIDE
                    + kk + (lane & 3) * 2;
                float2 v0 = *(const float2*)(ap);
                float2 v1 = *(const float2*)(ap + 8 * ASTRIDE);
                float2 v2 = *(const float2*)(ap + 8);
                float2 v3 = *(const float2*)(ap + 8 * ASTRIDE + 8);
                af[mf][0] = packh2(v0.x, v0.y);
                af[mf][1] = packh2(v1.x, v1.y);
                af[mf][2] = packh2(v2.x, v2.y);
                af[mf][3] = packh2(v3.x, v3.y);
            }
            uint32_t bf[8][2];
            #pragma unroll
            for (int nf = 0; nf < 8; nf++) {
                const __half* bp = Bs
                    + (wn * 64 + nf * 8 + (lane >> 2)) * BSTRIDE_H
                    + kk + (lane & 3) * 2;
                bf[nf][0] = *(const uint32_t*)(bp);
                bf[nf][1] = *(const uint32_t*)(bp + 8);
            }
            #pragma unroll
            for (int mf = 0; mf < 2; mf++)
                #pragma unroll
                for (int nf = 0; nf < 8; nf++)
                    mma_f16(acc[mf][nf], af[mf], bf[nf]);
        }

        if ((c & 15) != 15) continue;

        // ================= tile epilogue (tile = c >> 4) =================
        const int tile = c >> 4;
        const float* Ebt = E + (rowbase + (size_t)tile * 128) * ENC;

        #pragma unroll
        for (int mf = 0; mf < 2; mf++) {
            #pragma unroll
            for (int h = 0; h < 2; h++) {
                float ps = 0.f;
                #pragma unroll
                for (int nf = 0; nf < 8; nf++) {
                    const int u0 = wn * 64 + nf * 8 + 2 * (lane & 3);
                    ps = fmaf(wv_s[u0],
                              tanh_approx(q_s[u0] + acc[mf][nf][2 * h]), ps);
                    ps = fmaf(wv_s[u0 + 1],
                              tanh_approx(q_s[u0 + 1] + acc[mf][nf][2 * h + 1]), ps);
                }
                ps += __shfl_xor_sync(0xffffffffu, ps, 1);
                ps += __shfl_xor_sync(0xffffffffu, ps, 2);
                if ((lane & 3) == 0) {
                    const int row = wm * 32 + mf * 16 + (lane >> 2) + 8 * h;
                    s_red[row][wn] = ps;
                }
            }
        }
        // reset accumulators for next tile
        #pragma unroll
        for (int mf = 0; mf < 2; mf++)
            #pragma unroll
            for (int nf = 0; nf < 8; nf++)
                { acc[mf][nf][0]=0.f; acc[mf][nf][1]=0.f;
                  acc[mf][nf][2]=0.f; acc[mf][nf][3]=0.f; }
        __syncthreads();
        if (tid < 128) {
            const float s = s_red[tid][0] + s_red[tid][1];
            const float p = __expf(s + bv0);
            p_tile[tid] = p;
            l_acc += p;
            attn_out[rowbase + (size_t)tile * 128 + tid] = p;
        }
        __syncthreads();

        // context accumulation (E re-read, L2-hot; overlaps in-flight cp.async)
        {
            const float2* E2 = (const float2*)Ebt;
            #pragma unroll 4
            for (int t = 0; t < 128; t++) {
                const float pt = p_tile[t];
                const float2 v = E2[(size_t)t * 256 + tid];
                ctx.x = fmaf(pt, v.x, ctx.x);
                ctx.y = fmaf(pt, v.y, ctx.y);
            }
        }
        __syncthreads();
    }

    // reduce l, write partials
    red[tid] = l_acc;
    __syncthreads();
    for (int off = 128; off > 0; off >>= 1) {
        if (tid < off) red[tid] += red[tid + off];
        __syncthreads();
    }
    if (tid == 0) g_l_part[blockIdx.x] = red[0];
    ((float2*)(g_ctx_part + (size_t)blockIdx.x * ENC))[tid] = ctx;
}

// ---------------------------------------------------------------------------
// K2: combine quarters -> normalized context; normalize attn.
//   grid = 256: block (b, quarter). quarter 0 also writes ctx.
// ---------------------------------------------------------------------------
__global__ void combine_norm_kernel(float* __restrict__ ctx_out,
                                    float* __restrict__ attn) {
    const int b = blockIdx.x >> 2;
    const int quarter = blockIdx.x & 3;
    const int e = threadIdx.x;   // 512
    float l = g_l_part[b * NCHUNK + 0] + g_l_part[b * NCHUNK + 1]
            + g_l_part[b * NCHUNK + 2] + g_l_part[b * NCHUNK + 3];
    const float linv = 1.f / l;
    if (quarter == 0) {
        float c = 0.f;
        #pragma unroll
        for (int qc = 0; qc < NCHUNK; qc++)
            c += g_ctx_part[(size_t)(b * NCHUNK + qc) * ENC + e];
        ctx_out[b * ENC + e] = c * linv;
    }
    attn[(size_t)b * TT + quarter * 512 + e] *= linv;
}

// ---------------------------------------------------------------------------
extern "C" void kernel_launch(void* const* d_in, const int* in_sizes, int n_in,
                              void* d_out, int out_size) {
    const float* dh = (const float*)d_in[0];
    const float* E  = (const float*)d_in[1];
    const float* Wa = (const float*)d_in[2];
    const float* ba = (const float*)d_in[3];
    const float* Wb = (const float*)d_in[4];
    const float* bb = (const float*)d_in[5];
    const float* Wv = (const float*)d_in[6];
    const float* bv = (const float*)d_in[7];

    float* out      = (float*)d_out;
    float* ctx_out  = out;                 // [64,512]
    float* attn_out = out + BB * ENC;      // [64,2048]

    cudaFuncSetAttribute(fused_kernel,
                         cudaFuncAttributeMaxDynamicSharedMemorySize, DYN_BYTES);

    prep_kernel<<<BB + 128, 512>>>(dh, Wa, ba, bb, Wb);
    fused_kernel<<<NCTA, 256, DYN_BYTES>>>(E, Wv, bv, attn_out);
    combine_norm_kernel<<<NCTA, 512>>>(ctx_out, attn_out);
}

// round 13
// speedup vs baseline: 4.5543x; 1.4261x over previous
#include <cuda_runtime.h>
#include <cuda_fp16.h>
#include <math.h>
#include <stdint.h>

// Problem dims
#define BB   64
#define TT   2048
#define ENC  512
#define DEC  512
#define UU   128
#define BT   (BB*TT)

// Tiling
#define ASTRIDE     40                    // fp32 per A smem row (32 + 8 pad) — conflict-free
#define A_BYTES     (128 * ASTRIDE * 4)   // 20480
#define A_FLOATS    (128 * ASTRIDE)
#define BSTRIDE_H   40                    // fp16 per B smem row — conflict-free
#define B_BYTES     (128 * BSTRIDE_H * 2) // 10240
#define STAGE_BYTES (A_BYTES + B_BYTES)   // 30720
#define STAGE_FLOATS (STAGE_BYTES / 4)
#define NSTAGE      3
#define DYN_BYTES   (NSTAGE * STAGE_BYTES + 1024)

#define NSPLIT 16                         // T-sixteenths per batch (1 tile each)
#define NCTA   (BB * NSPLIT)              // 1024 CTAs
#define NCHUNKS_TOTAL 16                  // k-chunks per tile

// scratch (__device__ globals per allocation-free rule)
__device__ float  g_q_part[2][BB * UU];   // e-half partials of q
__device__ __half g_WbtH[UU * ENC];       // Wb transposed [n][k], fp16
__device__ float  g_ctx_part[NCTA * ENC]; // 2 MB
__device__ float  g_l_part[NCTA];

// ---------------------------------------------------------------------------
// helpers
// ---------------------------------------------------------------------------
__device__ __forceinline__ uint32_t smem_u32(const void* p) {
    uint32_t a;
    asm("{ .reg .u64 t; cvta.to.shared.u64 t, %1; cvt.u32.u64 %0, t; }"
        : "=r"(a) : "l"(p));
    return a;
}
__device__ __forceinline__ void cpy16(uint32_t dst, const void* src) {
    asm volatile("cp.async.cg.shared.global [%0], [%1], 16;"
                 :: "r"(dst), "l"(src) : "memory");
}
__device__ __forceinline__ void cp_commit() {
    asm volatile("cp.async.commit_group;" ::: "memory");
}
__device__ __forceinline__ void cp_wait1() {
    asm volatile("cp.async.wait_group 1;" ::: "memory");
}
__device__ __forceinline__ float tanh_approx(float x) {
    float y; asm("tanh.approx.f32 %0, %1;" : "=f"(y) : "f"(x));
    return y;
}
__device__ __forceinline__ uint32_t packh2(float lo, float hi) {
    __half2 h = __float22half2_rn(make_float2(lo, hi));
    return *(uint32_t*)&h;
}
__device__ __forceinline__ void mma_f16(float* c, const uint32_t* a,
                                        const uint32_t* b) {
    asm volatile(
        "mma.sync.aligned.m16n8k16.row.col.f32.f16.f16.f32 "
        "{%0,%1,%2,%3}, {%4,%5,%6,%7}, {%8,%9}, {%0,%1,%2,%3};\n"
        : "+f"(c[0]), "+f"(c[1]), "+f"(c[2]), "+f"(c[3])
        : "r"(a[0]), "r"(a[1]), "r"(a[2]), "r"(a[3]),
          "r"(b[0]), "r"(b[1]));
}

// ---------------------------------------------------------------------------
// K0: prep, 512 threads/block.
//   Blocks 0..127:   q partials. block = (b, ehalf); threads (u, eg of 4):
//                    chain length 64; smem reduce -> g_q_part[ehalf][b][u].
//   Blocks 128..255: WbtH[n][k] = fp16(Wb[k][n]) — one element per thread
//                    (128 blocks x 512 threads = 65536, proven R11 mapping).
// ---------------------------------------------------------------------------
__global__ void prep_kernel(const float* __restrict__ dh,
                            const float* __restrict__ Wa,
                            const float* __restrict__ ba,
                            const float* __restrict__ bb,
                            const float* __restrict__ Wb) {
    if (blockIdx.x < 2 * BB) {
        __shared__ float part[512];
        const int b     = blockIdx.x >> 1;
        const int ehalf = blockIdx.x & 1;
        const int u  = threadIdx.x & 127;
        const int eg = threadIdx.x >> 7;          // 0..3
        const int e0 = ehalf * 256 + eg * 64;
        float acc = 0.f;
        const float* dhb = dh + b * DEC + e0;
        const float* wap = Wa + (size_t)e0 * UU + u;
        #pragma unroll 16
        for (int e = 0; e < 64; e++)
            acc = fmaf(dhb[e], wap[(size_t)e * UU], acc);
        part[threadIdx.x] = acc;
        __syncthreads();
        if (threadIdx.x < 128) {
            float q = part[threadIdx.x] + part[threadIdx.x + 128]
                    + part[threadIdx.x + 256] + part[threadIdx.x + 384];
            if (ehalf == 0) q += ba[u] + bb[u];
            g_q_part[ehalf][b * UU + u] = q;
        }
    } else {
        const int i = (blockIdx.x - 2 * BB) * 512 + threadIdx.x;   // 0..65535
        const int k = i >> 7, n = i & 127;
        g_WbtH[(size_t)n * ENC + k] = __float2half_rn(Wb[i]);
    }
}

// ---------------------------------------------------------------------------
// K1 (fused): CTA = (b, sixteenth) -> one 128-row tile, 16 k-chunks.
//   3-stage cp.async pipeline, mma.sync fp16 k16 (warp grid 4Mx2N),
//   fused tanh/exp epilogue + L2-hot context accumulation.
// ---------------------------------------------------------------------------
extern __shared__ float dynsmem[];

__global__ void __launch_bounds__(256, 2)
fused_kernel(const float* __restrict__ E,
             const float* __restrict__ Wv,
             const float* __restrict__ bv,
             float* __restrict__ attn_out) {
    __shared__ float q_s[UU], wv_s[UU];
    __shared__ float p_tile[128];
    __shared__ float s_red[128][3];
    __shared__ float red[256];

    const int tid  = threadIdx.x;
    const int lane = tid & 31;
    const int wid  = tid >> 5;
    const int wm   = wid >> 1;           // 0..3  (M quarter: 32 rows)
    const int wn   = wid & 1;            // 0..1  (N half: 64 cols)
    const int b    = blockIdx.x >> 4;
    const int six  = blockIdx.x & 15;
    const size_t rowbase = (size_t)b * TT + (size_t)six * 128;
    const float* Ebt = E + rowbase * ENC;

    const uint32_t dynb = (smem_u32(dynsmem) + 1023) & ~1023u;
    const int dynoff = (int)(dynb - smem_u32(dynsmem)) >> 2;

    if (tid < UU) {
        q_s[tid]  = g_q_part[0][b * UU + tid] + g_q_part[1][b * UU + tid];
        wv_s[tid] = Wv[tid];
    }
    const float bv0 = bv[0];

    // chunk loader
    auto load_chunk = [&](int c) {
        const uint32_t sb = dynb + (c % NSTAGE) * STAGE_BYTES;
        const uint32_t bbs = sb + A_BYTES;
        const float*  Asrc = Ebt + c * 32;
        const __half* Bsrc = g_WbtH + c * 32;
        #pragma unroll
        for (int it = 0; it < 4; it++) {
            int idx = tid + it * 256;
            int r = idx >> 3, q = idx & 7;
            cpy16(sb + r * 160 + q * 16, Asrc + (size_t)r * ENC + q * 4);
        }
        #pragma unroll
        for (int it = 0; it < 2; it++) {
            int idx = tid + it * 256;
            int n = idx >> 2, q = idx & 3;
            cpy16(bbs + n * 80 + q * 16, Bsrc + (size_t)n * ENC + q * 8);
        }
        cp_commit();
    };

    load_chunk(0);
    load_chunk(1);

    float acc[2][8][4];
    #pragma unroll
    for (int mf = 0; mf < 2; mf++)
        #pragma unroll
        for (int nf = 0; nf < 8; nf++)
            { acc[mf][nf][0]=0.f; acc[mf][nf][1]=0.f;
              acc[mf][nf][2]=0.f; acc[mf][nf][3]=0.f; }

    for (int c = 0; c < NCHUNKS_TOTAL; c++) {
        cp_wait1();            // chunk c resident
        __syncthreads();       // all warps done with stage (c-1)%3
        if (c + 2 < NCHUNKS_TOTAL) load_chunk(c + 2);
        else                       cp_commit();   // uniform group count

        const float*  As = dynsmem + dynoff + (c % NSTAGE) * STAGE_FLOATS;
        const __half* Bs = (const __half*)(As + A_FLOATS);

        #pragma unroll
        for (int ks = 0; ks < 2; ks++) {
            const int kk = ks * 16;
            uint32_t af[2][4];
            #pragma unroll
            for (int mf = 0; mf < 2; mf++) {
                const float* ap = As
                    + (wm * 32 + mf * 16 + (lane >> 2)) * ASTRIDE
                    + kk + (lane & 3) * 2;
                float2 v0 = *(const float2*)(ap);
                float2 v1 = *(const float2*)(ap + 8 * ASTRIDE);
                float2 v2 = *(const float2*)(ap + 8);
                float2 v3 = *(const float2*)(ap + 8 * ASTRIDE + 8);
                af[mf][0] = packh2(v0.x, v0.y);
                af[mf][1] = packh2(v1.x, v1.y);
                af[mf][2] = packh2(v2.x, v2.y);
                af[mf][3] = packh2(v3.x, v3.y);
            }
            uint32_t bf[8][2];
            #pragma unroll
            for (int nf = 0; nf < 8; nf++) {
                const __half* bp = Bs
                    + (wn * 64 + nf * 8 + (lane >> 2)) * BSTRIDE_H
                    + kk + (lane & 3) * 2;
                bf[nf][0] = *(const uint32_t*)(bp);
                bf[nf][1] = *(const uint32_t*)(bp + 8);
            }
            #pragma unroll
            for (int mf = 0; mf < 2; mf++)
                #pragma unroll
                for (int nf = 0; nf < 8; nf++)
                    mma_f16(acc[mf][nf], af[mf], bf[nf]);
        }
    }

    // ================= epilogue =================
    #pragma unroll
    for (int mf = 0; mf < 2; mf++) {
        #pragma unroll
        for (int h = 0; h < 2; h++) {
            float ps = 0.f;
            #pragma unroll
            for (int nf = 0; nf < 8; nf++) {
                const int u0 = wn * 64 + nf * 8 + 2 * (lane & 3);
                ps = fmaf(wv_s[u0],
                          tanh_approx(q_s[u0] + acc[mf][nf][2 * h]), ps);
                ps = fmaf(wv_s[u0 + 1],
                          tanh_approx(q_s[u0 + 1] + acc[mf][nf][2 * h + 1]), ps);
            }
            ps += __shfl_xor_sync(0xffffffffu, ps, 1);
            ps += __shfl_xor_sync(0xffffffffu, ps, 2);
            if ((lane & 3) == 0) {
                const int row = wm * 32 + mf * 16 + (lane >> 2) + 8 * h;
                s_red[row][wn] = ps;
            }
        }
    }
    __syncthreads();
    float l_acc = 0.f;
    if (tid < 128) {
        const float s = s_red[tid][0] + s_red[tid][1];
        const float p = __expf(s + bv0);
        p_tile[tid] = p;
        l_acc = p;
        attn_out[rowbase + tid] = p;
    }
    __syncthreads();

    // context accumulation (E re-read, L2-hot)
    float2 ctx = make_float2(0.f, 0.f);
    {
        const float2* E2 = (const float2*)Ebt;
        #pragma unroll 4
        for (int t = 0; t < 128; t++) {
            const float pt = p_tile[t];
            const float2 v = E2[(size_t)t * 256 + tid];
            ctx.x = fmaf(pt, v.x, ctx.x);
            ctx.y = fmaf(pt, v.y, ctx.y);
        }
    }

    // reduce l, write partials
    red[tid] = l_acc;
    __syncthreads();
    for (int off = 128; off > 0; off >>= 1) {
        if (tid < off) red[tid] += red[tid + off];
        __syncthreads();
    }
    if (tid == 0) g_l_part[blockIdx.x] = red[0];
    ((float2*)(g_ctx_part + (size_t)blockIdx.x * ENC))[tid] = ctx;
}

// ---------------------------------------------------------------------------
// K2: combine sixteenths -> normalized context; normalize attn.
//   grid = 256: block (b, quarter of attn). quarter 0 also writes ctx.
// ---------------------------------------------------------------------------
__global__ void combine_norm_kernel(float* __restrict__ ctx_out,
                                    float* __restrict__ attn) {
    const int b = blockIdx.x >> 2;
    const int quarter = blockIdx.x & 3;
    const int e = threadIdx.x;   // 512
    float l = 0.f;
    #pragma unroll
    for (int s = 0; s < NSPLIT; s++) l += g_l_part[b * NSPLIT + s];
    const float linv = 1.f / l;
    if (quarter == 0) {
        float c = 0.f;
        #pragma unroll
        for (int s = 0; s < NSPLIT; s++)
            c += g_ctx_part[(size_t)(b * NSPLIT + s) * ENC + e];
        ctx_out[b * ENC + e] = c * linv;
    }
    attn[(size_t)b * TT + quarter * 512 + e] *= linv;
}

// ---------------------------------------------------------------------------
extern "C" void kernel_launch(void* const* d_in, const int* in_sizes, int n_in,
                              void* d_out, int out_size) {
    const float* dh = (const float*)d_in[0];
    const float* E  = (const float*)d_in[1];
    const float* Wa = (const float*)d_in[2];
    const float* ba = (const float*)d_in[3];
    const float* Wb = (const float*)d_in[4];
    const float* bb = (const float*)d_in[5];
    const float* Wv = (const float*)d_in[6];
    const float* bv = (const float*)d_in[7];

    float* out      = (float*)d_out;
    float* ctx_out  = out;                 // [64,512]
    float* attn_out = out + BB * ENC;      // [64,2048]

    cudaFuncSetAttribute(fused_kernel,
                         cudaFuncAttributeMaxDynamicSharedMemorySize, DYN_BYTES);

    prep_kernel<<<2 * BB + 128, 512>>>(dh, Wa, ba, bb, Wb);
    fused_kernel<<<NCTA, 256, DYN_BYTES>>>(E, Wv, bv, attn_out);
    combine_norm_kernel<<<4 * BB, 512>>>(ctx_out, attn_out);
}

// round 15
// speedup vs baseline: 4.8195x; 1.0582x over previous
#include <cuda_runtime.h>
#include <cuda_fp16.h>
#include <math.h>
#include <stdint.h>

// Problem dims
#define BB   64
#define TT   2048
#define ENC  512
#define DEC  512
#define UU   128
#define BT   (BB*TT)

// Tiling
#define ASTRIDE     40                    // fp32 per A smem row (32 + 8 pad) — conflict-free
#define A_BYTES     (128 * ASTRIDE * 4)   // 20480
#define A_FLOATS    (128 * ASTRIDE)
#define BCH_BYTES   8192                  // permuted B fragment table per chunk
#define STAGE_BYTES (A_BYTES + BCH_BYTES) // 28672
#define STAGE_FLOATS (STAGE_BYTES / 4)
#define NSTAGE      3
#define DYN_BYTES   (NSTAGE * STAGE_BYTES + 1024)

#define NSPLIT 16                         // T-sixteenths per batch (1 tile each)
#define NCTA   (BB * NSPLIT)              // 1024 CTAs
#define NCHUNKS_TOTAL 16                  // k-chunks per tile

// scratch (__device__ globals per allocation-free rule)
__device__ float    g_q_part[4][BB * UU]; // e-quarter partials of q
__device__ uint32_t g_WbF[16 * 2 * 8 * 32 * 4];  // fragment-permuted Wb (128 KB)
__device__ float    g_ctx_part[NCTA * ENC];      // 2 MB
__device__ float    g_l_part[NCTA];

// ---------------------------------------------------------------------------
// helpers
// ---------------------------------------------------------------------------
__device__ __forceinline__ uint32_t smem_u32(const void* p) {
    uint32_t a;
    asm("{ .reg .u64 t; cvta.to.shared.u64 t, %1; cvt.u32.u64 %0, t; }"
        : "=r"(a) : "l"(p));
    return a;
}
__device__ __forceinline__ void cpy16(uint32_t dst, const void* src) {
    asm volatile("cp.async.cg.shared.global [%0], [%1], 16;"
                 :: "r"(dst), "l"(src) : "memory");
}
__device__ __forceinline__ void cp_commit() {
    asm volatile("cp.async.commit_group;" ::: "memory");
}
__device__ __forceinline__ void cp_wait1() {
    asm volatile("cp.async.wait_group 1;" ::: "memory");
}
__device__ __forceinline__ float tanh_approx(float x) {
    float y; asm("tanh.approx.f32 %0, %1;" : "=f"(y) : "f"(x));
    return y;
}
__device__ __forceinline__ uint32_t packh2(float lo, float hi) {
    __half2 h = __float22half2_rn(make_float2(lo, hi));
    return *(uint32_t*)&h;
}
__device__ __forceinline__ void lds128(uint32_t* r, uint32_t addr) {
    asm volatile("ld.shared.v4.u32 {%0,%1,%2,%3}, [%4];"
                 : "=r"(r[0]), "=r"(r[1]), "=r"(r[2]), "=r"(r[3]) : "r"(addr));
}
__device__ __forceinline__ void mma_f16(float* c, const uint32_t* a,
                                        const uint32_t* b) {
    asm volatile(
        "mma.sync.aligned.m16n8k16.row.col.f32.f16.f16.f32 "
        "{%0,%1,%2,%3}, {%4,%5,%6,%7}, {%8,%9}, {%0,%1,%2,%3};\n"
        : "+f"(c[0]), "+f"(c[1]), "+f"(c[2]), "+f"(c[3])
        : "r"(a[0]), "r"(a[1]), "r"(a[2]), "r"(a[3]),
          "r"(b[0]), "r"(b[1]));
}

// ---------------------------------------------------------------------------
// K0: prep, 512 threads/block.
//   Blocks 0..255:   q partials. block = (b, eq of 4); threads (u, eg of 4):
//                    chain length 32; smem reduce -> g_q_part[eq][b][u].
//   Blocks 256..271: fragment-permuted B table. slot s = ((c*2+wn)*8+nf)*32+lane
//                    holds halfs Wb[k][n] for n = wn*64+nf*8+(lane>>2),
//                    k = c*32 + (lane&3)*2 + {0,1,8,9} (ks0) / +16 (ks1).
// ---------------------------------------------------------------------------
__global__ void prep_kernel(const float* __restrict__ dh,
                            const float* __restrict__ Wa,
                            const float* __restrict__ ba,
                            const float* __restrict__ bb,
                            const float* __restrict__ Wb) {
    if (blockIdx.x < 4 * BB) {
        __shared__ float part[512];
        const int b  = blockIdx.x >> 2;
        const int eq = blockIdx.x & 3;
        const int u  = threadIdx.x & 127;
        const int eg = threadIdx.x >> 7;          // 0..3
        const int e0 = eq * 128 + eg * 32;
        float acc = 0.f;
        const float* dhb = dh + b * DEC + e0;
        const float* wap = Wa + (size_t)e0 * UU + u;
        #pragma unroll
        for (int e = 0; e < 32; e++)
            acc = fmaf(dhb[e], wap[(size_t)e * UU], acc);
        part[threadIdx.x] = acc;
        __syncthreads();
        if (threadIdx.x < 128) {
            float q = part[threadIdx.x] + part[threadIdx.x + 128]
                    + part[threadIdx.x + 256] + part[threadIdx.x + 384];
            if (eq == 0) q += ba[u] + bb[u];
            g_q_part[eq][b * UU + u] = q;
        }
    } else {
        const int s = (blockIdx.x - 4 * BB) * 512 + threadIdx.x;   // 0..8191
        const int lane = s & 31;
        const int nf   = (s >> 5) & 7;
        const int wn   = (s >> 8) & 1;
        const int c    = s >> 9;
        const int n  = wn * 64 + nf * 8 + (lane >> 2);
        const int kb = c * 32 + (lane & 3) * 2;
        uint4 v;
        v.x = packh2(Wb[(size_t)kb * UU + n],        Wb[(size_t)(kb + 1) * UU + n]);
        v.y = packh2(Wb[(size_t)(kb + 8) * UU + n],  Wb[(size_t)(kb + 9) * UU + n]);
        v.z = packh2(Wb[(size_t)(kb + 16) * UU + n], Wb[(size_t)(kb + 17) * UU + n]);
        v.w = packh2(Wb[(size_t)(kb + 24) * UU + n], Wb[(size_t)(kb + 25) * UU + n]);
        *(uint4*)&g_WbF[(size_t)s * 4] = v;
    }
}

// ---------------------------------------------------------------------------
// K1 (fused): CTA = (b, sixteenth) -> one 128-row tile, 16 k-chunks.
//   3-stage cp.async pipeline, mma.sync fp16 k16 (warp grid 4Mx2N),
//   B frags via one LDS.128 per nf per chunk (fragment-permuted table),
//   fused tanh/exp epilogue + L2-hot context accumulation.
// ---------------------------------------------------------------------------
extern __shared__ float dynsmem[];

__global__ void __launch_bounds__(256, 2)
fused_kernel(const float* __restrict__ E,
             const float* __restrict__ Wv,
             const float* __restrict__ bv,
             float* __restrict__ attn_out) {
    __shared__ float q_s[UU], wv_s[UU];
    __shared__ float p_tile[128];
    __shared__ float s_red[128][3];
    __shared__ float red[256];

    const int tid  = threadIdx.x;
    const int lane = tid & 31;
    const int wid  = tid >> 5;
    const int wm   = wid >> 1;           // 0..3  (M quarter: 32 rows)
    const int wn   = wid & 1;            // 0..1  (N half: 64 cols)
    const int b    = blockIdx.x >> 4;
    const int six  = blockIdx.x & 15;
    const size_t rowbase = (size_t)b * TT + (size_t)six * 128;
    const float* Ebt = E + rowbase * ENC;

    const uint32_t dynb = (smem_u32(dynsmem) + 1023) & ~1023u;
    const int dynoff = (int)(dynb - smem_u32(dynsmem)) >> 2;

    if (tid < UU) {
        q_s[tid]  = g_q_part[0][b * UU + tid] + g_q_part[1][b * UU + tid]
                  + g_q_part[2][b * UU + tid] + g_q_part[3][b * UU + tid];
        wv_s[tid] = Wv[tid];
    }
    const float bv0 = bv[0];

    // chunk loader: A tile (128x32 fp32) + permuted B fragment table (8 KB)
    auto load_chunk = [&](int c) {
        const uint32_t sb = dynb + (c % NSTAGE) * STAGE_BYTES;
        const uint32_t bbs = sb + A_BYTES;
        const float* Asrc = Ebt + c * 32;
        const char*  Bsrc = (const char*)g_WbF + (size_t)c * BCH_BYTES;
        #pragma unroll
        for (int it = 0; it < 4; it++) {
            int idx = tid + it * 256;
            int r = idx >> 3, q = idx & 7;
            cpy16(sb + r * 160 + q * 16, Asrc + (size_t)r * ENC + q * 4);
        }
        #pragma unroll
        for (int it = 0; it < 2; it++) {
            int idx = tid + it * 256;
            cpy16(bbs + idx * 16, Bsrc + idx * 16);
        }
        cp_commit();
    };

    load_chunk(0);
    load_chunk(1);

    float acc[2][8][4];
    #pragma unroll
    for (int mf = 0; mf < 2; mf++)
        #pragma unroll
        for (int nf = 0; nf < 8; nf++)
            { acc[mf][nf][0]=0.f; acc[mf][nf][1]=0.f;
              acc[mf][nf][2]=0.f; acc[mf][nf][3]=0.f; }

    const uint32_t b_slot_off = (uint32_t)(((wn * 8) * 32 + lane) * 16);

    for (int c = 0; c < NCHUNKS_TOTAL; c++) {
        cp_wait1();            // chunk c resident
        __syncthreads();       // all warps done with stage (c-1)%3
        if (c + 2 < NCHUNKS_TOTAL) load_chunk(c + 2);
        else                       cp_commit();   // uniform group count

        const float*   As = dynsmem + dynoff + (c % NSTAGE) * STAGE_FLOATS;
        const uint32_t Bs = dynb + (c % NSTAGE) * STAGE_BYTES + A_BYTES;

        // B fragments for the whole chunk: 8 LDS.128
        uint32_t bq[8][4];
        #pragma unroll
        for (int nf = 0; nf < 8; nf++)
            lds128(bq[nf], Bs + b_slot_off + (uint32_t)(nf * 32 * 16));

        #pragma unroll
        for (int ks = 0; ks < 2; ks++) {
            const int kk = ks * 16;
            uint32_t af[2][4];
            #pragma unroll
            for (int mf = 0; mf < 2; mf++) {
                const float* ap = As
                    + (wm * 32 + mf * 16 + (lane >> 2)) * ASTRIDE
                    + kk + (lane & 3) * 2;
                float2 v0 = *(const float2*)(ap);
                float2 v1 = *(const float2*)(ap + 8 * ASTRIDE);
                float2 v2 = *(const float2*)(ap + 8);
                float2 v3 = *(const float2*)(ap + 8 * ASTRIDE + 8);
                af[mf][0] = packh2(v0.x, v0.y);
                af[mf][1] = packh2(v1.x, v1.y);
                af[mf][2] = packh2(v2.x, v2.y);
                af[mf][3] = packh2(v3.x, v3.y);
            }
            #pragma unroll
            for (int mf = 0; mf < 2; mf++)
                #pragma unroll
                for (int nf = 0; nf < 8; nf++)
                    mma_f16(acc[mf][nf], af[mf], &bq[nf][ks * 2]);
        }
    }

    // ================= epilogue =================
    #pragma unroll
    for (int mf = 0; mf < 2; mf++) {
        #pragma unroll
        for (int h = 0; h < 2; h++) {
            float ps = 0.f;
            #pragma unroll
            for (int nf = 0; nf < 8; nf++) {
                const int u0 = wn * 64 + nf * 8 + 2 * (lane & 3);
                ps = fmaf(wv_s[u0],
                          tanh_approx(q_s[u0] + acc[mf][nf][2 * h]), ps);
                ps = fmaf(wv_s[u0 + 1],
                          tanh_approx(q_s[u0 + 1] + acc[mf][nf][2 * h + 1]), ps);
            }
            ps += __shfl_xor_sync(0xffffffffu, ps, 1);
            ps += __shfl_xor_sync(0xffffffffu, ps, 2);
            if ((lane & 3) == 0) {
                const int row = wm * 32 + mf * 16 + (lane >> 2) + 8 * h;
                s_red[row][wn] = ps;
            }
        }
    }
    __syncthreads();
    float l_acc = 0.f;
    if (tid < 128) {
        const float s = s_red[tid][0] + s_red[tid][1];
        const float p = __expf(s + bv0);
        p_tile[tid] = p;
        l_acc = p;
        attn_out[rowbase + tid] = p;
    }
    __syncthreads();

    // context accumulation (E re-read, L2-hot)
    float2 ctx = make_float2(0.f, 0.f);
    {
        const float2* E2 = (const float2*)Ebt;
        #pragma unroll 4
        for (int t = 0; t < 128; t++) {
            const float pt = p_tile[t];
            const float2 v = E2[(size_t)t * 256 + tid];
            ctx.x = fmaf(pt, v.x, ctx.x);
            ctx.y = fmaf(pt, v.y, ctx.y);
        }
    }

    // reduce l, write partials
    red[tid] = l_acc;
    __syncthreads();
    for (int off = 128; off > 0; off >>= 1) {
        if (tid < off) red[tid] += red[tid + off];
        __syncthreads();
    }
    if (tid == 0) g_l_part[blockIdx.x] = red[0];
    ((float2*)(g_ctx_part + (size_t)blockIdx.x * ENC))[tid] = ctx;
}

// ---------------------------------------------------------------------------
// K2: combine sixteenths -> normalized context; normalize attn.
//   grid = 256: block (b, quarter of attn). quarter 0 also writes ctx.
// ---------------------------------------------------------------------------
__global__ void combine_norm_kernel(float* __restrict__ ctx_out,
                                    float* __restrict__ attn) {
    const int b = blockIdx.x >> 2;
    const int quarter = blockIdx.x & 3;
    const int e = threadIdx.x;   // 512
    float l = 0.f;
    #pragma unroll
    for (int s = 0; s < NSPLIT; s++) l += g_l_part[b * NSPLIT + s];
    const float linv = 1.f / l;
    if (quarter == 0) {
        float c = 0.f;
        #pragma unroll
        for (int s = 0; s < NSPLIT; s++)
            c += g_ctx_part[(size_t)(b * NSPLIT + s) * ENC + e];
        ctx_out[b * ENC + e] = c * linv;
    }
    attn[(size_t)b * TT + quarter * 512 + e] *= linv;
}

// ---------------------------------------------------------------------------
extern "C" void kernel_launch(void* const* d_in, const int* in_sizes, int n_in,
                              void* d_out, int out_size) {
    const float* dh = (const float*)d_in[0];
    const float* E  = (const float*)d_in[1];
    const float* Wa = (const float*)d_in[2];
    const float* ba = (const float*)d_in[3];
    const float* Wb = (const float*)d_in[4];
    const float* bb = (const float*)d_in[5];
    const float* Wv = (const float*)d_in[6];
    const float* bv = (const float*)d_in[7];

    float* out      = (float*)d_out;
    float* ctx_out  = out;                 // [64,512]
    float* attn_out = out + BB * ENC;      // [64,2048]

    cudaFuncSetAttribute(fused_kernel,
                         cudaFuncAttributeMaxDynamicSharedMemorySize, DYN_BYTES);

    prep_kernel<<<4 * BB + 16, 512>>>(dh, Wa, ba, bb, Wb);
    fused_kernel<<<NCTA, 256, DYN_BYTES>>>(E, Wv, bv, attn_out);
    combine_norm_kernel<<<4 * BB, 512>>>(ctx_out, attn_out);
}

// round 16
// speedup vs baseline: 5.8225x; 1.2081x over previous
#include <cuda_runtime.h>
#include <cuda_fp16.h>
#include <math.h>
#include <stdint.h>

// Problem dims
#define BB   64
#define TT   2048
#define ENC  512
#define DEC  512
#define UU   128
#define BT   (BB*TT)

// Tiling
#define ASTRIDE     40                    // fp32 per A smem row (32 + 8 pad) — conflict-free
#define A_BYTES     (128 * ASTRIDE * 4)   // 20480
#define A_FLOATS    (128 * ASTRIDE)
#define BCH_BYTES   8192                  // permuted B fragment table per chunk
#define STAGE_BYTES (A_BYTES + BCH_BYTES) // 28672
#define STAGE_FLOATS (STAGE_BYTES / 4)
#define NSTAGE      3
#define DYN_BYTES   (NSTAGE * STAGE_BYTES + 1024)

#define NSPLIT 16                         // T-sixteenths per batch (1 tile each)
#define NCTA   (BB * NSPLIT)              // 1024 CTAs
#define NCHUNKS_TOTAL 16                  // k-chunks per tile

// scratch (__device__ globals per allocation-free rule)
__device__ float    g_q_part[4][BB * UU]; // e-quarter partials of q
__device__ uint32_t g_WbF[16 * 2 * 8 * 32 * 4];  // fragment-permuted Wb (128 KB)
__device__ float    g_ctx_part[NCTA * ENC];      // 2 MB
__device__ float    g_l_part[NCTA];
__device__ int      g_cnt[BB];            // zero-init; reset after use each launch

// ---------------------------------------------------------------------------
// helpers
// ---------------------------------------------------------------------------
__device__ __forceinline__ uint32_t smem_u32(const void* p) {
    uint32_t a;
    asm("{ .reg .u64 t; cvta.to.shared.u64 t, %1; cvt.u32.u64 %0, t; }"
        : "=r"(a) : "l"(p));
    return a;
}
__device__ __forceinline__ void cpy16(uint32_t dst, const void* src) {
    asm volatile("cp.async.cg.shared.global [%0], [%1], 16;"
                 :: "r"(dst), "l"(src) : "memory");
}
__device__ __forceinline__ void cp_commit() {
    asm volatile("cp.async.commit_group;" ::: "memory");
}
__device__ __forceinline__ void cp_wait1() {
    asm volatile("cp.async.wait_group 1;" ::: "memory");
}
__device__ __forceinline__ float tanh_approx(float x) {
    float y; asm("tanh.approx.f32 %0, %1;" : "=f"(y) : "f"(x));
    return y;
}
__device__ __forceinline__ uint32_t packh2(float lo, float hi) {
    __half2 h = __float22half2_rn(make_float2(lo, hi));
    return *(uint32_t*)&h;
}
__device__ __forceinline__ void lds128(uint32_t* r, uint32_t addr) {
    asm volatile("ld.shared.v4.u32 {%0,%1,%2,%3}, [%4];"
                 : "=r"(r[0]), "=r"(r[1]), "=r"(r[2]), "=r"(r[3]) : "r"(addr));
}
__device__ __forceinline__ void mma_f16(float* c, const uint32_t* a,
                                        const uint32_t* b) {
    asm volatile(
        "mma.sync.aligned.m16n8k16.row.col.f32.f16.f16.f32 "
        "{%0,%1,%2,%3}, {%4,%5,%6,%7}, {%8,%9}, {%0,%1,%2,%3};\n"
        : "+f"(c[0]), "+f"(c[1]), "+f"(c[2]), "+f"(c[3])
        : "r"(a[0]), "r"(a[1]), "r"(a[2]), "r"(a[3]),
          "r"(b[0]), "r"(b[1]));
}

// ---------------------------------------------------------------------------
// K0: prep, 512 threads/block.
//   Blocks 0..255:   q partials. block = (b, eq of 4); threads (u, eg of 4):
//                    chain length 32; smem reduce -> g_q_part[eq][b][u].
//   Blocks 256..271: fragment-permuted B table (verified R15 mapping).
// ---------------------------------------------------------------------------
__global__ void prep_kernel(const float* __restrict__ dh,
                            const float* __restrict__ Wa,
                            const float* __restrict__ ba,
                            const float* __restrict__ bb,
                            const float* __restrict__ Wb) {
    if (blockIdx.x < 4 * BB) {
        __shared__ float part[512];
        const int b  = blockIdx.x >> 2;
        const int eq = blockIdx.x & 3;
        const int u  = threadIdx.x & 127;
        const int eg = threadIdx.x >> 7;          // 0..3
        const int e0 = eq * 128 + eg * 32;
        float acc = 0.f;
        const float* dhb = dh + b * DEC + e0;
        const float* wap = Wa + (size_t)e0 * UU + u;
        #pragma unroll
        for (int e = 0; e < 32; e++)
            acc = fmaf(dhb[e], wap[(size_t)e * UU], acc);
        part[threadIdx.x] = acc;
        __syncthreads();
        if (threadIdx.x < 128) {
            float q = part[threadIdx.x] + part[threadIdx.x + 128]
                    + part[threadIdx.x + 256] + part[threadIdx.x + 384];
            if (eq == 0) q += ba[u] + bb[u];
            g_q_part[eq][b * UU + u] = q;
        }
    } else {
        const int s = (blockIdx.x - 4 * BB) * 512 + threadIdx.x;   // 0..8191
        const int lane = s & 31;
        const int nf   = (s >> 5) & 7;
        const int wn   = (s >> 8) & 1;
        const int c    = s >> 9;
        const int n  = wn * 64 + nf * 8 + (lane >> 2);
        const int kb = c * 32 + (lane & 3) * 2;
        uint4 v;
        v.x = packh2(Wb[(size_t)kb * UU + n],        Wb[(size_t)(kb + 1) * UU + n]);
        v.y = packh2(Wb[(size_t)(kb + 8) * UU + n],  Wb[(size_t)(kb + 9) * UU + n]);
        v.z = packh2(Wb[(size_t)(kb + 16) * UU + n], Wb[(size_t)(kb + 17) * UU + n]);
        v.w = packh2(Wb[(size_t)(kb + 24) * UU + n], Wb[(size_t)(kb + 25) * UU + n]);
        *(uint4*)&g_WbF[(size_t)s * 4] = v;
    }
}

// ---------------------------------------------------------------------------
// K1 (fused): CTA = (b, sixteenth) -> one 128-row tile, 16 k-chunks.
//   3-stage cp.async pipeline, mma.sync fp16 k16 (warp grid 4Mx2N),
//   B frags via one LDS.128 per nf per chunk, fused tanh/exp epilogue,
//   float4 context pass, and last-CTA-per-batch combine+normalize.
// ---------------------------------------------------------------------------
extern __shared__ float dynsmem[];

__global__ void __launch_bounds__(256, 2)
fused_kernel(const float* __restrict__ E,
             const float* __restrict__ Wv,
             const float* __restrict__ bv,
             float* __restrict__ ctx_out,
             float* __restrict__ attn_out) {
    __shared__ float  q_s[UU], wv_s[UU];
    __shared__ float  p_tile[128];
    __shared__ float  s_red[128][3];
    __shared__ float4 ctx_red[256];
    __shared__ int    is_last;

    const int tid  = threadIdx.x;
    const int lane = tid & 31;
    const int wid  = tid >> 5;
    const int wm   = wid >> 1;           // 0..3  (M quarter: 32 rows)
    const int wn   = wid & 1;            // 0..1  (N half: 64 cols)
    const int b    = blockIdx.x >> 4;
    const int six  = blockIdx.x & 15;
    const size_t rowbase = (size_t)b * TT + (size_t)six * 128;
    const float* Ebt = E + rowbase * ENC;

    const uint32_t dynb = (smem_u32(dynsmem) + 1023) & ~1023u;
    const int dynoff = (int)(dynb - smem_u32(dynsmem)) >> 2;

    if (tid < UU) {
        q_s[tid]  = g_q_part[0][b * UU + tid] + g_q_part[1][b * UU + tid]
                  + g_q_part[2][b * UU + tid] + g_q_part[3][b * UU + tid];
        wv_s[tid] = Wv[tid];
    }
    const float bv0 = bv[0];

    // chunk loader: A tile (128x32 fp32) + permuted B fragment table (8 KB)
    auto load_chunk = [&](int c) {
        const uint32_t sb = dynb + (c % NSTAGE) * STAGE_BYTES;
        const uint32_t bbs = sb + A_BYTES;
        const float* Asrc = Ebt + c * 32;
        const char*  Bsrc = (const char*)g_WbF + (size_t)c * BCH_BYTES;
        #pragma unroll
        for (int it = 0; it < 4; it++) {
            int idx = tid + it * 256;
            int r = idx >> 3, q = idx & 7;
            cpy16(sb + r * 160 + q * 16, Asrc + (size_t)r * ENC + q * 4);
        }
        #pragma unroll
        for (int it = 0; it < 2; it++) {
            int idx = tid + it * 256;
            cpy16(bbs + idx * 16, Bsrc + idx * 16);
        }
        cp_commit();
    };

    load_chunk(0);
    load_chunk(1);

    float acc[2][8][4];
    #pragma unroll
    for (int mf = 0; mf < 2; mf++)
        #pragma unroll
        for (int nf = 0; nf < 8; nf++)
            { acc[mf][nf][0]=0.f; acc[mf][nf][1]=0.f;
              acc[mf][nf][2]=0.f; acc[mf][nf][3]=0.f; }

    const uint32_t b_slot_off = (uint32_t)(((wn * 8) * 32 + lane) * 16);

    for (int c = 0; c < NCHUNKS_TOTAL; c++) {
        cp_wait1();            // chunk c resident
        __syncthreads();       // all warps done with stage (c-1)%3
        if (c + 2 < NCHUNKS_TOTAL) load_chunk(c + 2);
        else                       cp_commit();   // uniform group count

        const float*   As = dynsmem + dynoff + (c % NSTAGE) * STAGE_FLOATS;
        const uint32_t Bs = dynb + (c % NSTAGE) * STAGE_BYTES + A_BYTES;

        // B fragments for the whole chunk: 8 LDS.128
        uint32_t bq[8][4];
        #pragma unroll
        for (int nf = 0; nf < 8; nf++)
            lds128(bq[nf], Bs + b_slot_off + (uint32_t)(nf * 32 * 16));

        #pragma unroll
        for (int ks = 0; ks < 2; ks++) {
            const int kk = ks * 16;
            uint32_t af[2][4];
            #pragma unroll
            for (int mf = 0; mf < 2; mf++) {
                const float* ap = As
                    + (wm * 32 + mf * 16 + (lane >> 2)) * ASTRIDE
                    + kk + (lane & 3) * 2;
                float2 v0 = *(const float2*)(ap);
                float2 v1 = *(const float2*)(ap + 8 * ASTRIDE);
                float2 v2 = *(const float2*)(ap + 8);
                float2 v3 = *(const float2*)(ap + 8 * ASTRIDE + 8);
                af[mf][0] = packh2(v0.x, v0.y);
                af[mf][1] = packh2(v1.x, v1.y);
                af[mf][2] = packh2(v2.x, v2.y);
                af[mf][3] = packh2(v3.x, v3.y);
            }
            #pragma unroll
            for (int mf = 0; mf < 2; mf++)
                #pragma unroll
                for (int nf = 0; nf < 8; nf++)
                    mma_f16(acc[mf][nf], af[mf], &bq[nf][ks * 2]);
        }
    }

    // ================= epilogue: s = Wv . tanh(q + k) =================
    #pragma unroll
    for (int mf = 0; mf < 2; mf++) {
        #pragma unroll
        for (int h = 0; h < 2; h++) {
            float ps = 0.f;
            #pragma unroll
            for (int nf = 0; nf < 8; nf++) {
                const int u0 = wn * 64 + nf * 8 + 2 * (lane & 3);
                ps = fmaf(wv_s[u0],
                          tanh_approx(q_s[u0] + acc[mf][nf][2 * h]), ps);
                ps = fmaf(wv_s[u0 + 1],
                          tanh_approx(q_s[u0 + 1] + acc[mf][nf][2 * h + 1]), ps);
            }
            ps += __shfl_xor_sync(0xffffffffu, ps, 1);
            ps += __shfl_xor_sync(0xffffffffu, ps, 2);
            if ((lane & 3) == 0) {
                const int row = wm * 32 + mf * 16 + (lane >> 2) + 8 * h;
                s_red[row][wn] = ps;
            }
        }
    }
    __syncthreads();
    if (tid < 128) {
        const float s = s_red[tid][0] + s_red[tid][1];
        const float p = __expf(s + bv0);
        p_tile[tid] = p;
        attn_out[rowbase + tid] = p;
    }
    __syncthreads();

    // l via warp-0 shuffle reduce
    if (wid == 0) {
        float pl = p_tile[lane] + p_tile[lane + 32]
                 + p_tile[lane + 64] + p_tile[lane + 96];
        #pragma unroll
        for (int off = 16; off > 0; off >>= 1)
            pl += __shfl_xor_sync(0xffffffffu, pl, off);
        if (lane == 0) g_l_part[blockIdx.x] = pl;
    }

    // context accumulation (E re-read, L2-hot): float4, row-halved
    {
        const int ehalf = tid >> 7;            // row half (0/1)
        const int e4    = tid & 127;           // float4 column index
        const float4* E4 = (const float4*)Ebt; // row stride 128 float4
        float4 cacc = make_float4(0.f, 0.f, 0.f, 0.f);
        #pragma unroll 8
        for (int t = 0; t < 64; t++) {
            const int row = ehalf * 64 + t;
            const float pt = p_tile[row];
            const float4 v = E4[(size_t)row * 128 + e4];
            cacc.x = fmaf(pt, v.x, cacc.x);
            cacc.y = fmaf(pt, v.y, cacc.y);
            cacc.z = fmaf(pt, v.z, cacc.z);
            cacc.w = fmaf(pt, v.w, cacc.w);
        }
        ctx_red[tid] = cacc;
    }
    __syncthreads();
    if (tid < 128) {
        const float4 a = ctx_red[tid];
        const float4 c2 = ctx_red[tid + 128];
        float4 r = make_float4(a.x + c2.x, a.y + c2.y, a.z + c2.z, a.w + c2.w);
        ((float4*)(g_ctx_part + (size_t)blockIdx.x * ENC))[tid] = r;
    }
    __syncthreads();          // all partial writes issued

    // ============ last-CTA-per-batch combine + normalize ============
    if (tid == 0) {
        __threadfence();       // publish partials + attn numerators
        const int old = atomicAdd(&g_cnt[b], 1);
        is_last = (old == NSPLIT - 1);
    }
    __syncthreads();
    if (is_last) {
        __threadfence();       // acquire other CTAs' writes
        float l = 0.f;
        #pragma unroll
        for (int s = 0; s < NSPLIT; s++) l += g_l_part[b * NSPLIT + s];
        const float linv = 1.f / l;
        #pragma unroll
        for (int i = 0; i < 2; i++) {
            const int e = tid + i * 256;
            float cacc = 0.f;
            #pragma unroll
            for (int s = 0; s < NSPLIT; s++)
                cacc += g_ctx_part[(size_t)(b * NSPLIT + s) * ENC + e];
            ctx_out[b * ENC + e] = cacc * linv;
        }
        #pragma unroll
        for (int i = 0; i < 8; i++)
            attn_out[(size_t)b * TT + tid + i * 256] *= linv;
        if (tid == 0) g_cnt[b] = 0;   // reset for next launch (idempotent)
    }
}

// ---------------------------------------------------------------------------
extern "C" void kernel_launch(void* const* d_in, const int* in_sizes, int n_in,
                              void* d_out, int out_size) {
    const float* dh = (const float*)d_in[0];
    const float* E  = (const float*)d_in[1];
    const float* Wa = (const float*)d_in[2];
    const float* ba = (const float*)d_in[3];
    const float* Wb = (const float*)d_in[4];
    const float* bb = (const float*)d_in[5];
    const float* Wv = (const float*)d_in[6];
    const float* bv = (const float*)d_in[7];

    float* out      = (float*)d_out;
    float* ctx_out  = out;                 // [64,512]
    float* attn_out = out + BB * ENC;      // [64,2048]

    cudaFuncSetAttribute(fused_kernel,
                         cudaFuncAttributeMaxDynamicSharedMemorySize, DYN_BYTES);

    prep_kernel<<<4 * BB + 16, 512>>>(dh, Wa, ba, bb, Wb);
    fused_kernel<<<NCTA, 256, DYN_BYTES>>>(E, Wv, bv, ctx_out, attn_out);
}